// round 13
// baseline (speedup 1.0000x reference)
#include <cuda_runtime.h>
#include <cuda_bf16.h>
#include <math.h>
#include <cstdint>

// Problem constants
#define BSZ 8
#define NN  15135
#define FF  64
#define GG  73
#define HH  256
#define HFCC 512
#define CCLS 2
#define EE  242160
#define KIN (FF + GG)        // 137
#define MM  (BSZ * NN)       // 121080
#define K1PAD 192            // layer-1 K padded to multiple of 64
#define SCANB 15             // ceil(NN/1024)

// ---------------- scratch (device globals; no dynamic alloc allowed) -------
__device__ int   d_degi[NN];
__device__ float d_dis[NN];
__device__ float d_deginv[NN];
__device__ int   d_csr_ptr[NN + 1];
__device__ int   d_rank[EE];          // per-edge rank within its dst column
__device__ int2  d_ew[EE];            // packed (src, weight-bits)
__device__ int   d_bsum[16];
__device__ __align__(16) __nv_bfloat16 d_hw[(size_t)MM * HH];
__device__ __align__(16) __nv_bfloat16 d_h1[(size_t)MM * HH];
__device__ __align__(16) __nv_bfloat16 d_h2[(size_t)MM * HH];
__device__ __align__(16) __nv_bfloat16 d_ag1[(size_t)MM * K1PAD];  // aggregated concat input
__device__ __align__(16) __nv_bfloat16 d_xb[(size_t)MM * FF];      // x in bf16
__device__ __align__(16) __nv_bfloat16 d_peb[(size_t)NN * GG];     // pe in bf16
__device__ __align__(16) __nv_bfloat16 d_wt1[HH * K1PAD];   // W1^T padded
__device__ __align__(16) __nv_bfloat16 d_wt2[HH * HH];      // W2^T
__device__ __align__(16) __nv_bfloat16 d_wt3[HH * HH];      // W3^T
__device__ float d_g[MM];
__device__ float d_zacc[BSZ * HFCC];

__device__ __forceinline__ float eluf(float v) {
    return v > 0.0f ? v : expm1f(v);
}

__device__ __forceinline__ float2 bf2f(uint32_t u) {
    __nv_bfloat162 m = *reinterpret_cast<__nv_bfloat162*>(&u);
    return make_float2(__bfloat162float(m.x), __bfloat162float(m.y));
}

// accumulate 8 bf16 lanes of u into a[0..7] with weight w
__device__ __forceinline__ void acc8(float* a, uint4 u, float w) {
    float2 m;
    m = bf2f(u.x); a[0] += w * m.x; a[1] += w * m.y;
    m = bf2f(u.y); a[2] += w * m.x; a[3] += w * m.y;
    m = bf2f(u.z); a[4] += w * m.x; a[5] += w * m.y;
    m = bf2f(u.w); a[6] += w * m.x; a[7] += w * m.y;
}

__device__ __forceinline__ uint4 pack8(const float* v) {
    uint4 o;
    __nv_bfloat162 p;
    p = __floats2bfloat162_rn(v[0], v[1]); o.x = *reinterpret_cast<uint32_t*>(&p);
    p = __floats2bfloat162_rn(v[2], v[3]); o.y = *reinterpret_cast<uint32_t*>(&p);
    p = __floats2bfloat162_rn(v[4], v[5]); o.z = *reinterpret_cast<uint32_t*>(&p);
    p = __floats2bfloat162_rn(v[6], v[7]); o.w = *reinterpret_cast<uint32_t*>(&p);
    return o;
}

// ---------------- fused prep: degree count(+rank) + converts + transposes --
#define XITEMS ((long long)MM * 8)
#define PEITEMS ((long long)NN * GG)
#define NB_DEG  ((EE + 255) / 256)                              // 946
#define NB_CONV ((int)((XITEMS + PEITEMS + 255) / 256))         // ~8100
#define NB_TR   (HH * 3)                                        // 768
#define NB_PREP (NB_DEG + NB_CONV + NB_TR)

__global__ __launch_bounds__(256) void prep_all_kernel(
    const int* __restrict__ ei,
    const float* __restrict__ x, const float* __restrict__ pe,
    const float* __restrict__ W1, const float* __restrict__ W2,
    const float* __restrict__ W3)
{
    const int bid = blockIdx.x;
    const int t   = threadIdx.x;
    if (bid < NB_DEG) {
        int e = bid * 256 + t;
        if (e < EE) d_rank[e] = atomicAdd(&d_degi[ei[EE + e]], 1);
    } else if (bid < NB_DEG + NB_CONV) {
        long long i = (long long)(bid - NB_DEG) * 256 + t;
        if (i < XITEMS) {
            const float4* src = reinterpret_cast<const float4*>(x) + 2 * i;
            float4 v0 = src[0], v1 = src[1];
            float v[8] = {v0.x, v0.y, v0.z, v0.w, v1.x, v1.y, v1.z, v1.w};
            reinterpret_cast<uint4*>(d_xb)[i] = pack8(v);
        } else {
            long long j = i - XITEMS;
            if (j < PEITEMS) d_peb[j] = __float2bfloat16_rn(pe[j]);
        }
    } else {
        int j = bid - NB_DEG - NB_CONV;     // 0..767
        int n = j & 255;
        int which = j >> 8;
        if (which == 0) {
            if (t < K1PAD)
                d_wt1[(size_t)n * K1PAD + t] =
                    __float2bfloat16_rn((t < KIN) ? W1[(size_t)t * HH + n] : 0.0f);
        } else {
            const float* W = (which == 1) ? W2 : W3;
            __nv_bfloat16* Wt = (which == 1) ? d_wt2 : d_wt3;
            Wt[(size_t)n * HH + t] = __float2bfloat16_rn(W[(size_t)t * HH + n]);
        }
    }
}

// ---------------- CSR scan ----------------
// stage 1: per-block local exclusive scan + block total + dis/deginv
__global__ __launch_bounds__(1024) void scan_part_kernel() {
    __shared__ int wsum[32];
    const int b = blockIdx.x, t = threadIdx.x;
    const int i = b * 1024 + t;
    const int lane = t & 31, warp = t >> 5;
    int v = 0;
    if (i < NN) {
        v = d_degi[i];
        float d = (float)v + 1.0f;
        d_dis[i]    = rsqrtf(d);
        d_deginv[i] = 1.0f / d;
    }
    int incl = v;
    #pragma unroll
    for (int o = 1; o < 32; o <<= 1) {
        int u = __shfl_up_sync(0xffffffffu, incl, o);
        if (lane >= o) incl += u;
    }
    if (lane == 31) wsum[warp] = incl;
    __syncthreads();
    if (warp == 0) {
        int s = wsum[lane];
        #pragma unroll
        for (int o = 1; o < 32; o <<= 1) {
            int u = __shfl_up_sync(0xffffffffu, s, o);
            if (lane >= o) s += u;
        }
        wsum[lane] = s;
    }
    __syncthreads();
    int wbase = (warp > 0) ? wsum[warp - 1] : 0;
    if (i < NN) d_csr_ptr[i] = wbase + incl - v;   // local exclusive
    if (t == 1023) d_bsum[b] = wsum[31];           // block total
}

// stage 2 (fused): each block re-scans the 15 block sums, adds its offset
__global__ __launch_bounds__(1024) void scan_final_kernel() {
    __shared__ int soff_sh;
    const int t = threadIdx.x;
    if (t < 32) {
        int v = (t < SCANB) ? d_bsum[t] : 0;
        int incl = v;
        #pragma unroll
        for (int o = 1; o < 32; o <<= 1) {
            int u = __shfl_up_sync(0xffffffffu, incl, o);
            if (t >= o) incl += u;
        }
        if (t == (int)blockIdx.x) soff_sh = incl - v;
        if (blockIdx.x == 0 && t == SCANB - 1) d_csr_ptr[NN] = incl;
    }
    __syncthreads();
    const int i = blockIdx.x * 1024 + t;
    if (i < NN) d_csr_ptr[i] += soff_sh;
}

// atomic-free fill: pos = csr_ptr[dst] + rank (recorded during count)
__global__ void fill_csr_kernel(const int* __restrict__ ei) {
    int e = blockIdx.x * blockDim.x + threadIdx.x;
    if (e < EE) {
        int r = ei[e];
        int c = ei[EE + e];
        int pos = d_csr_ptr[c] + d_rank[e];
        d_ew[pos] = make_int2(r, __float_as_int(d_dis[r] * d_dis[c]));
    }
}

// ---------------- layer-1 pre-aggregation (fused x + pe) -------------------
#define GXB ((NN + 1) / 2)
__global__ __launch_bounds__(128) void gather_l1_kernel() {
    const int t = threadIdx.x;
    if (blockIdx.x < GXB) {
        const int n = blockIdx.x * 2 + (t >> 6);
        if (n >= NN) return;
        const int b  = (t >> 3) & 7;
        const int fq = t & 7;
        const uint4* xp = reinterpret_cast<const uint4*>(d_xb) + (size_t)b * NN * 8;

        const int p0 = d_csr_ptr[n];
        const int p1 = d_csr_ptr[n + 1];
        float a[8];
        #pragma unroll
        for (int i = 0; i < 8; i++) a[i] = 0.0f;

        #pragma unroll 4
        for (int e = p0; e < p1; e++) {
            int2  ew = __ldg(&d_ew[e]);
            float w  = __int_as_float(ew.y);
            acc8(a, __ldg(xp + (size_t)ew.x * 8 + fq), w);
        }
        acc8(a, __ldg(xp + (size_t)n * 8 + fq), d_deginv[n]);   // self loop

        reinterpret_cast<uint4*>(d_ag1)[((size_t)b * NN + n) * 24 + fq] = pack8(a);
    } else {
        const int n = blockIdx.x - GXB;
        float a = 0.0f;
        if (t < GG) {
            const int p0 = d_csr_ptr[n];
            const int p1 = d_csr_ptr[n + 1];
            #pragma unroll 4
            for (int e = p0; e < p1; e++) {
                int2  ew = __ldg(&d_ew[e]);
                float w  = __int_as_float(ew.y);
                a += w * __bfloat162float(__ldg(&d_peb[(size_t)ew.x * GG + t]));
            }
            a += d_deginv[n] * __bfloat162float(__ldg(&d_peb[(size_t)n * GG + t]));
        }
        __nv_bfloat16 v = __float2bfloat16_rn(t < GG ? a : 0.0f);
        #pragma unroll
        for (int b = 0; b < BSZ; b++)
            d_ag1[((size_t)b * NN + n) * K1PAD + FF + t] = v;
    }
}

// ================= mma.sync bf16 GEMM, 128x256 CTA tile, 512 thr ===========
__device__ __forceinline__ void cp_async16(uint32_t dst, const void* src, int sz) {
    asm volatile("cp.async.cg.shared.global [%0], [%1], 16, %2;"
                 :: "r"(dst), "l"(src), "r"(sz) : "memory");
}

__device__ __forceinline__ void mma_bf16(float* c, const uint32_t* a, const uint32_t* b) {
    asm volatile(
        "mma.sync.aligned.m16n8k16.row.col.f32.bf16.bf16.f32 "
        "{%0,%1,%2,%3}, {%4,%5,%6,%7}, {%8,%9}, {%0,%1,%2,%3};"
        : "+f"(c[0]), "+f"(c[1]), "+f"(c[2]), "+f"(c[3])
        : "r"(a[0]), "r"(a[1]), "r"(a[2]), "r"(a[3]), "r"(b[0]), "r"(b[1]));
}

__device__ __forceinline__ void ldsm_x4(uint32_t* r, uint32_t addr) {
    asm volatile("ldmatrix.sync.aligned.m8n8.x4.shared.b16 {%0,%1,%2,%3}, [%4];"
                 : "=r"(r[0]), "=r"(r[1]), "=r"(r[2]), "=r"(r[3]) : "r"(addr));
}

#define GSTRU 36
#define GBUFU ((128 + 256) * GSTRU)          // u32 per buffer (A 128 + B 256 rows)
#define GSM_BYTES (2 * GBUFU * 4)            // 110592

// 16 warps: wm = wid>>3 (2), wn = wid&7 (8); warp tile 64x32. A read ONCE.
template <int KPAD, bool EPI>
__global__ __launch_bounds__(512, 1) void gemm_mma_kernel(
    const __nv_bfloat16* __restrict__ A, const __nv_bfloat16* __restrict__ Wt,
    __nv_bfloat16* __restrict__ hw, const float* __restrict__ bias)
{
    extern __shared__ uint32_t sm[];
    constexpr int NC = KPAD / 64;
    const int t    = threadIdx.x;
    const int lane = t & 31;
    const int wid  = t >> 5;
    const int wm   = wid >> 3;          // 0..1
    const int wn   = wid & 7;           // 0..7
    const int m0   = blockIdx.x * 128;
    const int g    = lane >> 2;
    const int q    = lane & 3;

    // ldmatrix per-lane address components (bytes, relative to buffer start)
    const int mid  = lane >> 3;          // matrix id 0..3
    const int mrow = lane & 7;           // row within 8x8 matrix
    const uint32_t offA = (uint32_t)(((wm * 64 + mrow + (mid & 1) * 8) * GSTRU
                                      + (mid >> 1) * 4) * 4);
    const uint32_t offB = (uint32_t)((128 * GSTRU
                                      + (wn * 32 + (mid >> 1) * 8 + mrow) * GSTRU
                                      + (mid & 1) * 4) * 4);
    const uint32_t sbase = (uint32_t)__cvta_generic_to_shared(sm);

    float acc[4][4][4];
    #pragma unroll
    for (int mi = 0; mi < 4; mi++)
        #pragma unroll
        for (int nj = 0; nj < 4; nj++)
            #pragma unroll
            for (int r = 0; r < 4; r++) acc[mi][nj][r] = 0.0f;

    auto load_chunk = [&](int ci, int buf) {
        uint32_t* dA = sm + buf * GBUFU;
        uint32_t* dB = dA + 128 * GSTRU;
        const int k0 = ci * 64;
        // A: 128 rows x 8 segs = 1024 -> 2 per thread
        #pragma unroll
        for (int r = 0; r < 2; r++) {
            int idx = t + r * 512;
            int row = idx >> 3;
            int seg = idx & 7;
            int m   = m0 + row;
            int valid = (m < MM);
            const __nv_bfloat16* srcA = A + (size_t)(valid ? m : 0) * KPAD + k0 + seg * 8;
            cp_async16((uint32_t)__cvta_generic_to_shared(dA + row * GSTRU + seg * 4),
                       srcA, valid ? 16 : 0);
        }
        // B: 256 rows x 8 segs = 2048 -> 4 per thread
        #pragma unroll
        for (int r = 0; r < 4; r++) {
            int idx = t + r * 512;
            int row = idx >> 3;
            int seg = idx & 7;
            const __nv_bfloat16* srcB = Wt + (size_t)row * KPAD + k0 + seg * 8;
            cp_async16((uint32_t)__cvta_generic_to_shared(dB + row * GSTRU + seg * 4),
                       srcB, 16);
        }
        asm volatile("cp.async.commit_group;" ::: "memory");
    };

    load_chunk(0, 0);
    if (NC > 1) load_chunk(1, 1);
    else        asm volatile("cp.async.commit_group;" ::: "memory");

    #pragma unroll 1
    for (int i = 0; i < NC; i++) {
        asm volatile("cp.async.wait_group 1;" ::: "memory");
        __syncthreads();
        const uint32_t bufb = sbase + (uint32_t)((i & 1) * GBUFU * 4);
        const uint32_t aA = bufb + offA;
        const uint32_t aB = bufb + offB;

        #pragma unroll
        for (int ks = 0; ks < 4; ks++) {
            const uint32_t kso = (uint32_t)(ks * 32);
            uint32_t a[4][4], b[4][2];
            #pragma unroll
            for (int mi = 0; mi < 4; mi++)
                ldsm_x4(a[mi], aA + (uint32_t)(mi * 16 * GSTRU * 4) + kso);
            {
                uint32_t r0[4], r1[4];
                ldsm_x4(r0, aB + kso);
                ldsm_x4(r1, aB + (uint32_t)(16 * GSTRU * 4) + kso);
                b[0][0] = r0[0]; b[0][1] = r0[1]; b[1][0] = r0[2]; b[1][1] = r0[3];
                b[2][0] = r1[0]; b[2][1] = r1[1]; b[3][0] = r1[2]; b[3][1] = r1[3];
            }
            #pragma unroll
            for (int mi = 0; mi < 4; mi++)
                #pragma unroll
                for (int nj = 0; nj < 4; nj++)
                    mma_bf16(acc[mi][nj], a[mi], b[nj]);
        }
        __syncthreads();
        if (i + 2 < NC) load_chunk(i + 2, i & 1);
        else            asm volatile("cp.async.commit_group;" ::: "memory");
    }

    __nv_bfloat162* hw2 = reinterpret_cast<__nv_bfloat162*>(hw);
    #pragma unroll
    for (int mi = 0; mi < 4; mi++) {
        int r = m0 + wm * 64 + mi * 16 + g;
        #pragma unroll
        for (int nj = 0; nj < 4; nj++) {
            int c  = wn * 32 + nj * 8 + q * 2;
            float v0 = acc[mi][nj][0], v1 = acc[mi][nj][1];
            float v2 = acc[mi][nj][2], v3 = acc[mi][nj][3];
            if (EPI) {
                float2 bv = *reinterpret_cast<const float2*>(bias + c);
                v0 = eluf(v0 + bv.x); v1 = eluf(v1 + bv.y);
                v2 = eluf(v2 + bv.x); v3 = eluf(v3 + bv.y);
            }
            int c2 = c >> 1;
            if (r < MM)
                hw2[(size_t)r * 128 + c2] = __floats2bfloat162_rn(v0, v1);
            if (r + 8 < MM)
                hw2[(size_t)(r + 8) * 128 + c2] = __floats2bfloat162_rn(v2, v3);
        }
    }
}

// ---------------- CSR gather (layers 2/3): LDG.128, 1 block/node ------------
template <bool FUSE_FC>
__global__ __launch_bounds__(128) void gather_kernel(
    const uint4* __restrict__ hw4, const float* __restrict__ bias,
    uint4* __restrict__ hout4,
    const float* __restrict__ fcW, const float* __restrict__ fcb)
{
    const int n  = blockIdx.x;
    const int t  = threadIdx.x;
    const int fq = t & 31;
    const int bp = t >> 5;
    const int b0 = 2 * bp, b1 = 2 * bp + 1;
    const size_t plane = (size_t)NN * 32;
    const uint4* hp0 = hw4 + (size_t)b0 * plane;
    const uint4* hp1 = hw4 + (size_t)b1 * plane;

    __shared__ float sfw[FUSE_FC ? 768 : 1];
    if (FUSE_FC) {
        #pragma unroll
        for (int i = t; i < 768; i += 128) sfw[i] = fcW[i];
        __syncthreads();
    }

    const int p0 = d_csr_ptr[n];
    const int p1 = d_csr_ptr[n + 1];

    float a0[8], a1v[8];
    #pragma unroll
    for (int i = 0; i < 8; i++) { a0[i] = 0.0f; a1v[i] = 0.0f; }

    #pragma unroll 4
    for (int e = p0; e < p1; e++) {
        int2  ew = __ldg(&d_ew[e]);
        float w  = __int_as_float(ew.y);
        size_t ro = (size_t)ew.x * 32 + fq;
        uint4 u0 = __ldg(hp0 + ro);
        uint4 u1 = __ldg(hp1 + ro);
        acc8(a0,  u0, w);
        acc8(a1v, u1, w);
    }

    const float di = d_deginv[n];
    const float4 bsa = reinterpret_cast<const float4*>(bias)[2 * fq];
    const float4 bsb = reinterpret_cast<const float4*>(bias)[2 * fq + 1];
    const float bs[8] = {bsa.x, bsa.y, bsa.z, bsa.w, bsb.x, bsb.y, bsb.z, bsb.w};

    size_t so = (size_t)n * 32 + fq;
    acc8(a0,  __ldg(hp0 + so), di);
    acc8(a1v, __ldg(hp1 + so), di);

    float v0[8], v1[8];
    #pragma unroll
    for (int i = 0; i < 8; i++) {
        v0[i] = eluf(a0[i]  + bs[i]);
        v1[i] = eluf(a1v[i] + bs[i]);
    }

    if (!FUSE_FC) {
        hout4[(size_t)b0 * plane + so] = pack8(v0);
        hout4[(size_t)b1 * plane + so] = pack8(v1);
    } else {
        const uint4* h1p0 = reinterpret_cast<const uint4*>(d_h1) + (size_t)b0 * plane;
        const uint4* h1p1 = reinterpret_cast<const uint4*>(d_h1) + (size_t)b1 * plane;
        const uint4* h2p0 = reinterpret_cast<const uint4*>(d_h2) + (size_t)b0 * plane;
        const uint4* h2p1 = reinterpret_cast<const uint4*>(d_h2) + (size_t)b1 * plane;
        float h10[8], h11[8], h20[8], h21[8];
        #pragma unroll
        for (int i = 0; i < 8; i++) { h10[i]=h11[i]=h20[i]=h21[i]=0.0f; }
        acc8(h10, __ldg(h1p0 + so), 1.0f); acc8(h11, __ldg(h1p1 + so), 1.0f);
        acc8(h20, __ldg(h2p0 + so), 1.0f); acc8(h21, __ldg(h2p1 + so), 1.0f);
        float g0 = 0.0f, g1 = 0.0f;
        #pragma unroll
        for (int i = 0; i < 8; i++) {
            const float* fw = &sfw[24 * fq + 3 * i];
            g0 += h10[i] * fw[0] + h20[i] * fw[1] + v0[i] * fw[2];
            g1 += h11[i] * fw[0] + h21[i] * fw[1] + v1[i] * fw[2];
        }
        #pragma unroll
        for (int o = 16; o > 0; o >>= 1) {
            g0 += __shfl_down_sync(0xffffffffu, g0, o);
            g1 += __shfl_down_sync(0xffffffffu, g1, o);
        }
        if (fq == 0) {
            float fb = fcb[0];
            d_g[(size_t)b0 * NN + n] = g0 + fb;
            d_g[(size_t)b1 * NN + n] = g1 + fb;
        }
    }
}

// ---------------- lin1: g[b,N] @ lin1_W[N,512] (accumulate) ----------------
#define NCH 256
__global__ __launch_bounds__(128) void lin1_kernel(const float* __restrict__ W)
{
    __shared__ float gs[BSZ][NCH];
    const int j  = blockIdx.x * 128 + threadIdx.x;
    const int n0 = blockIdx.y * NCH;
    const int cn = min(NCH, NN - n0);
    for (int idx = threadIdx.x; idx < BSZ * NCH; idx += 128) {
        int b  = idx >> 8;
        int nl = idx & (NCH - 1);
        gs[b][nl] = (nl < cn) ? d_g[(size_t)b * NN + n0 + nl] : 0.0f;
    }
    __syncthreads();
    float acc[BSZ];
    #pragma unroll
    for (int b = 0; b < BSZ; b++) acc[b] = 0.0f;
    for (int nl = 0; nl < cn; nl++) {
        float w = W[(size_t)(n0 + nl) * HFCC + j];
        #pragma unroll
        for (int b = 0; b < BSZ; b++) acc[b] += gs[b][nl] * w;
    }
    #pragma unroll
    for (int b = 0; b < BSZ; b++) atomicAdd(&d_zacc[b * HFCC + j], acc[b]);
}

// ---------------- lin2 + log_softmax ----------------
__global__ __launch_bounds__(256) void lin2_kernel(
    const float* __restrict__ lin1b, const float* __restrict__ lin2W,
    const float* __restrict__ lin2b, float* __restrict__ out)
{
    const int b = blockIdx.x;
    const int t = threadIdx.x;
    float s0 = 0.0f, s1 = 0.0f;
    for (int j = t; j < HFCC; j += 256) {
        float z = d_zacc[b * HFCC + j] + lin1b[j];
        z = eluf(z);
        s0 += z * lin2W[j * 2 + 0];
        s1 += z * lin2W[j * 2 + 1];
    }
    __shared__ float r0[256], r1[256];
    r0[t] = s0; r1[t] = s1;
    __syncthreads();
    for (int o = 128; o > 0; o >>= 1) {
        if (t < o) { r0[t] += r0[t + o]; r1[t] += r1[t + o]; }
        __syncthreads();
    }
    if (t == 0) {
        float o0 = r0[0] + lin2b[0];
        float o1 = r1[0] + lin2b[1];
        float mx = fmaxf(o0, o1);
        float lse = mx + logf(expf(o0 - mx) + expf(o1 - mx));
        out[b * CCLS + 0] = o0 - lse;
        out[b * CCLS + 1] = o1 - lse;
    }
}

// ---------------- launcher ----------------
extern "C" void kernel_launch(void* const* d_in, const int* in_sizes, int n_in,
                              void* d_out, int out_size)
{
    const float* x     = (const float*)d_in[0];
    const int*   ei    = (const int*)d_in[2];   // int32 [2, E]
    const float* pe    = (const float*)d_in[3];
    const float* W1    = (const float*)d_in[4];
    const float* b1    = (const float*)d_in[5];
    const float* W2    = (const float*)d_in[6];
    const float* b2    = (const float*)d_in[7];
    const float* W3    = (const float*)d_in[8];
    const float* b3    = (const float*)d_in[9];
    const float* fcW   = (const float*)d_in[10];
    const float* fcb   = (const float*)d_in[11];
    const float* lin1W = (const float*)d_in[12];
    const float* lin1b = (const float*)d_in[13];
    const float* lin2W = (const float*)d_in[14];
    const float* lin2b = (const float*)d_in[15];
    float* out = (float*)d_out;

    __nv_bfloat16 *hwp, *h1p, *h2p, *ag1p, *wt1p, *wt2p, *wt3p;
    cudaGetSymbolAddress((void**)&hwp,  d_hw);
    cudaGetSymbolAddress((void**)&h1p,  d_h1);
    cudaGetSymbolAddress((void**)&h2p,  d_h2);
    cudaGetSymbolAddress((void**)&ag1p, d_ag1);
    cudaGetSymbolAddress((void**)&wt1p, d_wt1);
    cudaGetSymbolAddress((void**)&wt2p, d_wt2);
    cudaGetSymbolAddress((void**)&wt3p, d_wt3);
    int* degip; float* zaccp;
    cudaGetSymbolAddress((void**)&degip, d_degi);
    cudaGetSymbolAddress((void**)&zaccp, d_zacc);

    cudaFuncSetAttribute((void*)gemm_mma_kernel<K1PAD, true>,
                         cudaFuncAttributeMaxDynamicSharedMemorySize, GSM_BYTES);
    cudaFuncSetAttribute((void*)gemm_mma_kernel<HH, false>,
                         cudaFuncAttributeMaxDynamicSharedMemorySize, GSM_BYTES);

    // fused prep: degree count(+rank) + converts + transposes
    cudaMemsetAsync(degip, 0, NN * sizeof(int));
    prep_all_kernel<<<NB_PREP, 256>>>(ei, x, pe, W1, W2, W3);

    // CSR scan + atomic-free fill
    scan_part_kernel<<<SCANB, 1024>>>();
    scan_final_kernel<<<SCANB, 1024>>>();
    fill_csr_kernel<<<(EE + 255) / 256, 256>>>(ei);

    // layer 1: fused pre-aggregation (x + pe), then GEMM with bias+ELU -> h1
    gather_l1_kernel<<<GXB + NN, 128>>>();

    const int ngrid = (MM + 127) / 128;   // 946, full 256-wide N per block
    const uint4* hw4 = reinterpret_cast<const uint4*>(hwp);
    uint4* h24 = reinterpret_cast<uint4*>(h2p);

    gemm_mma_kernel<K1PAD, true><<<ngrid, 512, GSM_BYTES>>>(ag1p, wt1p, h1p, b1);

    // layer 2
    gemm_mma_kernel<HH, false><<<ngrid, 512, GSM_BYTES>>>(h1p, wt2p, hwp, nullptr);
    gather_kernel<false><<<NN, 128>>>(hw4, b2, h24, nullptr, nullptr);

    // layer 3 (+ fused fc head -> d_g)
    gemm_mma_kernel<HH, false><<<ngrid, 512, GSM_BYTES>>>(h2p, wt3p, hwp, nullptr);
    gather_kernel<true><<<NN, 128>>>(hw4, b3, nullptr, fcW, fcb);

    // heads
    cudaMemsetAsync(zaccp, 0, BSZ * HFCC * sizeof(float));
    lin1_kernel<<<dim3(HFCC / 128, (NN + NCH - 1) / NCH), 128>>>(lin1W);
    lin2_kernel<<<BSZ, 256>>>(lin1b, lin2W, lin2b, out);
}

// round 14
// speedup vs baseline: 1.0574x; 1.0574x over previous
#include <cuda_runtime.h>
#include <cuda_bf16.h>
#include <math.h>
#include <cstdint>

// Problem constants
#define BSZ 8
#define NN  15135
#define FF  64
#define GG  73
#define HH  256
#define HFCC 512
#define CCLS 2
#define EE  242160
#define KIN (FF + GG)        // 137
#define MM  (BSZ * NN)       // 121080
#define K1PAD 192            // layer-1 K padded to multiple of 64
#define SCANB 15             // ceil(NN/1024)

// ---------------- scratch (device globals; no dynamic alloc allowed) -------
__device__ int   d_degi[NN];
__device__ float d_dis[NN];
__device__ float d_deginv[NN];
__device__ int   d_csr_ptr[NN + 1];
__device__ int   d_rank[EE];          // per-edge rank within its dst column
__device__ int2  d_ew[EE];            // packed (src, weight-bits)
__device__ int   d_bsum[16];
__device__ __align__(16) __nv_bfloat16 d_hw[(size_t)MM * HH];
__device__ __align__(16) __nv_bfloat16 d_h1[(size_t)MM * HH];
__device__ __align__(16) __nv_bfloat16 d_h2[(size_t)MM * HH];
__device__ __align__(16) __nv_bfloat16 d_ag1[(size_t)MM * K1PAD];  // aggregated concat input
__device__ __align__(16) __nv_bfloat16 d_xb[(size_t)MM * FF];      // x in bf16
__device__ __align__(16) __nv_bfloat16 d_peb[(size_t)NN * GG];     // pe in bf16
__device__ __align__(16) __nv_bfloat16 d_wt1[HH * K1PAD];   // W1^T padded
__device__ __align__(16) __nv_bfloat16 d_wt2[HH * HH];      // W2^T
__device__ __align__(16) __nv_bfloat16 d_wt3[HH * HH];      // W3^T
__device__ float d_g[MM];
__device__ float d_zacc[BSZ * HFCC];

__device__ __forceinline__ float eluf(float v) {
    return v > 0.0f ? v : expm1f(v);
}

__device__ __forceinline__ float2 bf2f(uint32_t u) {
    __nv_bfloat162 m = *reinterpret_cast<__nv_bfloat162*>(&u);
    return make_float2(__bfloat162float(m.x), __bfloat162float(m.y));
}

// accumulate 8 bf16 lanes of u into a[0..7] with weight w
__device__ __forceinline__ void acc8(float* a, uint4 u, float w) {
    float2 m;
    m = bf2f(u.x); a[0] += w * m.x; a[1] += w * m.y;
    m = bf2f(u.y); a[2] += w * m.x; a[3] += w * m.y;
    m = bf2f(u.z); a[4] += w * m.x; a[5] += w * m.y;
    m = bf2f(u.w); a[6] += w * m.x; a[7] += w * m.y;
}

__device__ __forceinline__ uint4 pack8(const float* v) {
    uint4 o;
    __nv_bfloat162 p;
    p = __floats2bfloat162_rn(v[0], v[1]); o.x = *reinterpret_cast<uint32_t*>(&p);
    p = __floats2bfloat162_rn(v[2], v[3]); o.y = *reinterpret_cast<uint32_t*>(&p);
    p = __floats2bfloat162_rn(v[4], v[5]); o.z = *reinterpret_cast<uint32_t*>(&p);
    p = __floats2bfloat162_rn(v[6], v[7]); o.w = *reinterpret_cast<uint32_t*>(&p);
    return o;
}

// ---------------- fused prep: degree count(+rank) + converts + transposes --
#define XITEMS ((long long)MM * 8)
#define PEITEMS ((long long)NN * GG)
#define NB_DEG  ((EE + 255) / 256)                              // 946
#define NB_CONV ((int)((XITEMS + PEITEMS + 255) / 256))         // ~8100
#define NB_TR   (HH * 3)                                        // 768
#define NB_PREP (NB_DEG + NB_CONV + NB_TR)

__global__ __launch_bounds__(256) void prep_all_kernel(
    const int* __restrict__ ei,
    const float* __restrict__ x, const float* __restrict__ pe,
    const float* __restrict__ W1, const float* __restrict__ W2,
    const float* __restrict__ W3)
{
    const int bid = blockIdx.x;
    const int t   = threadIdx.x;
    if (bid < NB_DEG) {
        int e = bid * 256 + t;
        if (e < EE) d_rank[e] = atomicAdd(&d_degi[ei[EE + e]], 1);
    } else if (bid < NB_DEG + NB_CONV) {
        long long i = (long long)(bid - NB_DEG) * 256 + t;
        if (i < XITEMS) {
            const float4* src = reinterpret_cast<const float4*>(x) + 2 * i;
            float4 v0 = src[0], v1 = src[1];
            float v[8] = {v0.x, v0.y, v0.z, v0.w, v1.x, v1.y, v1.z, v1.w};
            reinterpret_cast<uint4*>(d_xb)[i] = pack8(v);
        } else {
            long long j = i - XITEMS;
            if (j < PEITEMS) d_peb[j] = __float2bfloat16_rn(pe[j]);
        }
    } else {
        int j = bid - NB_DEG - NB_CONV;     // 0..767
        int n = j & 255;
        int which = j >> 8;
        if (which == 0) {
            if (t < K1PAD)
                d_wt1[(size_t)n * K1PAD + t] =
                    __float2bfloat16_rn((t < KIN) ? W1[(size_t)t * HH + n] : 0.0f);
        } else {
            const float* W = (which == 1) ? W2 : W3;
            __nv_bfloat16* Wt = (which == 1) ? d_wt2 : d_wt3;
            Wt[(size_t)n * HH + t] = __float2bfloat16_rn(W[(size_t)t * HH + n]);
        }
    }
}

// ---------------- CSR scan ----------------
// stage 1: per-block local exclusive scan + block total + dis/deginv
__global__ __launch_bounds__(1024) void scan_part_kernel() {
    __shared__ int wsum[32];
    const int b = blockIdx.x, t = threadIdx.x;
    const int i = b * 1024 + t;
    const int lane = t & 31, warp = t >> 5;
    int v = 0;
    if (i < NN) {
        v = d_degi[i];
        float d = (float)v + 1.0f;
        d_dis[i]    = rsqrtf(d);
        d_deginv[i] = 1.0f / d;
    }
    int incl = v;
    #pragma unroll
    for (int o = 1; o < 32; o <<= 1) {
        int u = __shfl_up_sync(0xffffffffu, incl, o);
        if (lane >= o) incl += u;
    }
    if (lane == 31) wsum[warp] = incl;
    __syncthreads();
    if (warp == 0) {
        int s = wsum[lane];
        #pragma unroll
        for (int o = 1; o < 32; o <<= 1) {
            int u = __shfl_up_sync(0xffffffffu, s, o);
            if (lane >= o) s += u;
        }
        wsum[lane] = s;
    }
    __syncthreads();
    int wbase = (warp > 0) ? wsum[warp - 1] : 0;
    if (i < NN) d_csr_ptr[i] = wbase + incl - v;   // local exclusive
    if (t == 1023) d_bsum[b] = wsum[31];           // block total
}

// stage 2 (fused): each block re-scans the 15 block sums, adds its offset
__global__ __launch_bounds__(1024) void scan_final_kernel() {
    __shared__ int soff_sh;
    const int t = threadIdx.x;
    if (t < 32) {
        int v = (t < SCANB) ? d_bsum[t] : 0;
        int incl = v;
        #pragma unroll
        for (int o = 1; o < 32; o <<= 1) {
            int u = __shfl_up_sync(0xffffffffu, incl, o);
            if (t >= o) incl += u;
        }
        if (t == (int)blockIdx.x) soff_sh = incl - v;
        if (blockIdx.x == 0 && t == SCANB - 1) d_csr_ptr[NN] = incl;
    }
    __syncthreads();
    const int i = blockIdx.x * 1024 + t;
    if (i < NN) d_csr_ptr[i] += soff_sh;
}

// atomic-free fill: pos = csr_ptr[dst] + rank (recorded during count)
__global__ void fill_csr_kernel(const int* __restrict__ ei) {
    int e = blockIdx.x * blockDim.x + threadIdx.x;
    if (e < EE) {
        int r = ei[e];
        int c = ei[EE + e];
        int pos = d_csr_ptr[c] + d_rank[e];
        d_ew[pos] = make_int2(r, __float_as_int(d_dis[r] * d_dis[c]));
    }
}

// ---------------- layer-1 pre-aggregation (fused x + pe) -------------------
#define GXB ((NN + 1) / 2)
__global__ __launch_bounds__(128) void gather_l1_kernel() {
    const int t = threadIdx.x;
    if (blockIdx.x < GXB) {
        const int n = blockIdx.x * 2 + (t >> 6);
        if (n >= NN) return;
        const int b  = (t >> 3) & 7;
        const int fq = t & 7;
        const uint4* xp = reinterpret_cast<const uint4*>(d_xb) + (size_t)b * NN * 8;

        const int p0 = d_csr_ptr[n];
        const int p1 = d_csr_ptr[n + 1];
        float a[8];
        #pragma unroll
        for (int i = 0; i < 8; i++) a[i] = 0.0f;

        #pragma unroll 4
        for (int e = p0; e < p1; e++) {
            int2  ew = __ldg(&d_ew[e]);
            float w  = __int_as_float(ew.y);
            acc8(a, __ldg(xp + (size_t)ew.x * 8 + fq), w);
        }
        acc8(a, __ldg(xp + (size_t)n * 8 + fq), d_deginv[n]);   // self loop

        reinterpret_cast<uint4*>(d_ag1)[((size_t)b * NN + n) * 24 + fq] = pack8(a);
    } else {
        const int n = blockIdx.x - GXB;
        float a = 0.0f;
        if (t < GG) {
            const int p0 = d_csr_ptr[n];
            const int p1 = d_csr_ptr[n + 1];
            #pragma unroll 4
            for (int e = p0; e < p1; e++) {
                int2  ew = __ldg(&d_ew[e]);
                float w  = __int_as_float(ew.y);
                a += w * __bfloat162float(__ldg(&d_peb[(size_t)ew.x * GG + t]));
            }
            a += d_deginv[n] * __bfloat162float(__ldg(&d_peb[(size_t)n * GG + t]));
        }
        __nv_bfloat16 v = __float2bfloat16_rn(t < GG ? a : 0.0f);
        #pragma unroll
        for (int b = 0; b < BSZ; b++)
            d_ag1[((size_t)b * NN + n) * K1PAD + FF + t] = v;
    }
}

// ================= mma.sync bf16 GEMM with ldmatrix (R12 config) ============
__device__ __forceinline__ void cp_async16(uint32_t dst, const void* src, int sz) {
    asm volatile("cp.async.cg.shared.global [%0], [%1], 16, %2;"
                 :: "r"(dst), "l"(src), "r"(sz) : "memory");
}

__device__ __forceinline__ void mma_bf16(float* c, const uint32_t* a, const uint32_t* b) {
    asm volatile(
        "mma.sync.aligned.m16n8k16.row.col.f32.bf16.bf16.f32 "
        "{%0,%1,%2,%3}, {%4,%5,%6,%7}, {%8,%9}, {%0,%1,%2,%3};"
        : "+f"(c[0]), "+f"(c[1]), "+f"(c[2]), "+f"(c[3])
        : "r"(a[0]), "r"(a[1]), "r"(a[2]), "r"(a[3]), "r"(b[0]), "r"(b[1]));
}

__device__ __forceinline__ void ldsm_x4(uint32_t* r, uint32_t addr) {
    asm volatile("ldmatrix.sync.aligned.m8n8.x4.shared.b16 {%0,%1,%2,%3}, [%4];"
                 : "=r"(r[0]), "=r"(r[1]), "=r"(r[2]), "=r"(r[3]) : "r"(addr));
}

#define GSTRU 36
#define GBUFU (2 * 128 * GSTRU)
#define GSM_BYTES (2 * GBUFU * 4)

// EPI: fused bias + ELU epilogue (layer 1 writes h1 directly)
template <int KPAD, bool EPI>
__global__ __launch_bounds__(256, 2) void gemm_mma_kernel(
    const __nv_bfloat16* __restrict__ A, const __nv_bfloat16* __restrict__ Wt,
    __nv_bfloat16* __restrict__ hw, const float* __restrict__ bias)
{
    extern __shared__ uint32_t sm[];
    constexpr int NC = KPAD / 64;
    const int t    = threadIdx.x;
    const int lane = t & 31;
    const int wid  = t >> 5;
    const int wm   = wid >> 2;
    const int wn   = wid & 3;
    const int m0   = blockIdx.x * 128;
    const int n0   = blockIdx.y * 128;
    const int g    = lane >> 2;
    const int q    = lane & 3;

    const int mid  = lane >> 3;          // matrix id 0..3
    const int mrow = lane & 7;           // row within 8x8 matrix
    const uint32_t offA = (uint32_t)(((wm * 64 + mrow + (mid & 1) * 8) * GSTRU
                                      + (mid >> 1) * 4) * 4);
    const uint32_t offB = (uint32_t)((128 * GSTRU
                                      + (wn * 32 + (mid >> 1) * 8 + mrow) * GSTRU
                                      + (mid & 1) * 4) * 4);
    const uint32_t sbase = (uint32_t)__cvta_generic_to_shared(sm);

    float acc[4][4][4];
    #pragma unroll
    for (int mi = 0; mi < 4; mi++)
        #pragma unroll
        for (int nj = 0; nj < 4; nj++)
            #pragma unroll
            for (int r = 0; r < 4; r++) acc[mi][nj][r] = 0.0f;

    auto load_chunk = [&](int ci, int buf) {
        uint32_t* dA = sm + buf * GBUFU;
        uint32_t* dB = dA + 128 * GSTRU;
        const int k0 = ci * 64;
        #pragma unroll
        for (int r = 0; r < 4; r++) {
            int idx = t + r * 256;
            int row = idx >> 3;
            int seg = idx & 7;
            int m   = m0 + row;
            int valid = (m < MM);
            const __nv_bfloat16* srcA = A + (size_t)(valid ? m : 0) * KPAD + k0 + seg * 8;
            cp_async16((uint32_t)__cvta_generic_to_shared(dA + row * GSTRU + seg * 4),
                       srcA, valid ? 16 : 0);
            const __nv_bfloat16* srcB = Wt + (size_t)(n0 + row) * KPAD + k0 + seg * 8;
            cp_async16((uint32_t)__cvta_generic_to_shared(dB + row * GSTRU + seg * 4),
                       srcB, 16);
        }
        asm volatile("cp.async.commit_group;" ::: "memory");
    };

    load_chunk(0, 0);
    if (NC > 1) load_chunk(1, 1);
    else        asm volatile("cp.async.commit_group;" ::: "memory");

    #pragma unroll 1
    for (int i = 0; i < NC; i++) {
        asm volatile("cp.async.wait_group 1;" ::: "memory");
        __syncthreads();
        const uint32_t bufb = sbase + (uint32_t)((i & 1) * GBUFU * 4);
        const uint32_t aA = bufb + offA;
        const uint32_t aB = bufb + offB;

        #pragma unroll
        for (int ks = 0; ks < 4; ks++) {
            const uint32_t kso = (uint32_t)(ks * 32);
            uint32_t a[4][4], b[4][2];
            #pragma unroll
            for (int mi = 0; mi < 4; mi++)
                ldsm_x4(a[mi], aA + (uint32_t)(mi * 16 * GSTRU * 4) + kso);
            {
                uint32_t r0[4], r1[4];
                ldsm_x4(r0, aB + kso);
                ldsm_x4(r1, aB + (uint32_t)(16 * GSTRU * 4) + kso);
                b[0][0] = r0[0]; b[0][1] = r0[1]; b[1][0] = r0[2]; b[1][1] = r0[3];
                b[2][0] = r1[0]; b[2][1] = r1[1]; b[3][0] = r1[2]; b[3][1] = r1[3];
            }
            #pragma unroll
            for (int mi = 0; mi < 4; mi++)
                #pragma unroll
                for (int nj = 0; nj < 4; nj++)
                    mma_bf16(acc[mi][nj], a[mi], b[nj]);
        }
        __syncthreads();
        if (i + 2 < NC) load_chunk(i + 2, i & 1);
        else            asm volatile("cp.async.commit_group;" ::: "memory");
    }

    __nv_bfloat162* hw2 = reinterpret_cast<__nv_bfloat162*>(hw);
    #pragma unroll
    for (int mi = 0; mi < 4; mi++) {
        int r = m0 + wm * 64 + mi * 16 + g;
        #pragma unroll
        for (int nj = 0; nj < 4; nj++) {
            int c  = n0 + wn * 32 + nj * 8 + q * 2;
            float v0 = acc[mi][nj][0], v1 = acc[mi][nj][1];
            float v2 = acc[mi][nj][2], v3 = acc[mi][nj][3];
            if (EPI) {
                float2 bv = *reinterpret_cast<const float2*>(bias + c);
                v0 = eluf(v0 + bv.x); v1 = eluf(v1 + bv.y);
                v2 = eluf(v2 + bv.x); v3 = eluf(v3 + bv.y);
            }
            int c2 = c >> 1;
            if (r < MM)
                hw2[(size_t)r * 128 + c2] = __floats2bfloat162_rn(v0, v1);
            if (r + 8 < MM)
                hw2[(size_t)(r + 8) * 128 + c2] = __floats2bfloat162_rn(v2, v3);
        }
    }
}

// ---------------- CSR gather (layers 2/3): 2 nodes per 256-thr block --------
template <bool FUSE_FC>
__global__ __launch_bounds__(256) void gather_kernel(
    const uint4* __restrict__ hw4, const float* __restrict__ bias,
    uint4* __restrict__ hout4,
    const float* __restrict__ fcW, const float* __restrict__ fcb)
{
    const int t  = threadIdx.x;
    const int n  = blockIdx.x * 2 + (t >> 7);   // node for this half-block
    const int th = t & 127;                     // thread within half
    const int fq = th & 31;
    const int bp = th >> 5;
    const int b0 = 2 * bp, b1 = 2 * bp + 1;
    const size_t plane = (size_t)NN * 32;
    const uint4* hp0 = hw4 + (size_t)b0 * plane;
    const uint4* hp1 = hw4 + (size_t)b1 * plane;

    __shared__ float sfw[FUSE_FC ? 768 : 1];
    if (FUSE_FC) {
        #pragma unroll
        for (int i = t; i < 768; i += 256) sfw[i] = fcW[i];
        __syncthreads();
    }
    if (n >= NN) return;

    const int p0 = d_csr_ptr[n];
    const int p1 = d_csr_ptr[n + 1];

    float a0[8], a1v[8];
    #pragma unroll
    for (int i = 0; i < 8; i++) { a0[i] = 0.0f; a1v[i] = 0.0f; }

    #pragma unroll 4
    for (int e = p0; e < p1; e++) {
        int2  ew = __ldg(&d_ew[e]);
        float w  = __int_as_float(ew.y);
        size_t ro = (size_t)ew.x * 32 + fq;
        uint4 u0 = __ldg(hp0 + ro);
        uint4 u1 = __ldg(hp1 + ro);
        acc8(a0,  u0, w);
        acc8(a1v, u1, w);
    }

    const float di = d_deginv[n];
    const float4 bsa = reinterpret_cast<const float4*>(bias)[2 * fq];
    const float4 bsb = reinterpret_cast<const float4*>(bias)[2 * fq + 1];
    const float bs[8] = {bsa.x, bsa.y, bsa.z, bsa.w, bsb.x, bsb.y, bsb.z, bsb.w};

    size_t so = (size_t)n * 32 + fq;
    acc8(a0,  __ldg(hp0 + so), di);
    acc8(a1v, __ldg(hp1 + so), di);

    float v0[8], v1[8];
    #pragma unroll
    for (int i = 0; i < 8; i++) {
        v0[i] = eluf(a0[i]  + bs[i]);
        v1[i] = eluf(a1v[i] + bs[i]);
    }

    if (!FUSE_FC) {
        hout4[(size_t)b0 * plane + so] = pack8(v0);
        hout4[(size_t)b1 * plane + so] = pack8(v1);
    } else {
        const uint4* h1p0 = reinterpret_cast<const uint4*>(d_h1) + (size_t)b0 * plane;
        const uint4* h1p1 = reinterpret_cast<const uint4*>(d_h1) + (size_t)b1 * plane;
        const uint4* h2p0 = reinterpret_cast<const uint4*>(d_h2) + (size_t)b0 * plane;
        const uint4* h2p1 = reinterpret_cast<const uint4*>(d_h2) + (size_t)b1 * plane;
        float h10[8], h11[8], h20[8], h21[8];
        #pragma unroll
        for (int i = 0; i < 8; i++) { h10[i]=h11[i]=h20[i]=h21[i]=0.0f; }
        acc8(h10, __ldg(h1p0 + so), 1.0f); acc8(h11, __ldg(h1p1 + so), 1.0f);
        acc8(h20, __ldg(h2p0 + so), 1.0f); acc8(h21, __ldg(h2p1 + so), 1.0f);
        float g0 = 0.0f, g1 = 0.0f;
        #pragma unroll
        for (int i = 0; i < 8; i++) {
            const float* fw = &sfw[24 * fq + 3 * i];
            g0 += h10[i] * fw[0] + h20[i] * fw[1] + v0[i] * fw[2];
            g1 += h11[i] * fw[0] + h21[i] * fw[1] + v1[i] * fw[2];
        }
        #pragma unroll
        for (int o = 16; o > 0; o >>= 1) {
            g0 += __shfl_down_sync(0xffffffffu, g0, o);
            g1 += __shfl_down_sync(0xffffffffu, g1, o);
        }
        if (fq == 0) {
            float fb = fcb[0];
            d_g[(size_t)b0 * NN + n] = g0 + fb;
            d_g[(size_t)b1 * NN + n] = g1 + fb;
        }
    }
}

// ---------------- lin1: g[b,N] @ lin1_W[N,512] (accumulate) ----------------
#define NCH 256
__global__ __launch_bounds__(128) void lin1_kernel(const float* __restrict__ W)
{
    __shared__ float gs[BSZ][NCH];
    const int j  = blockIdx.x * 128 + threadIdx.x;
    const int n0 = blockIdx.y * NCH;
    const int cn = min(NCH, NN - n0);
    for (int idx = threadIdx.x; idx < BSZ * NCH; idx += 128) {
        int b  = idx >> 8;
        int nl = idx & (NCH - 1);
        gs[b][nl] = (nl < cn) ? d_g[(size_t)b * NN + n0 + nl] : 0.0f;
    }
    __syncthreads();
    float acc[BSZ];
    #pragma unroll
    for (int b = 0; b < BSZ; b++) acc[b] = 0.0f;
    for (int nl = 0; nl < cn; nl++) {
        float w = W[(size_t)(n0 + nl) * HFCC + j];
        #pragma unroll
        for (int b = 0; b < BSZ; b++) acc[b] += gs[b][nl] * w;
    }
    #pragma unroll
    for (int b = 0; b < BSZ; b++) atomicAdd(&d_zacc[b * HFCC + j], acc[b]);
}

// ---------------- lin2 + log_softmax ----------------
__global__ __launch_bounds__(256) void lin2_kernel(
    const float* __restrict__ lin1b, const float* __restrict__ lin2W,
    const float* __restrict__ lin2b, float* __restrict__ out)
{
    const int b = blockIdx.x;
    const int t = threadIdx.x;
    float s0 = 0.0f, s1 = 0.0f;
    for (int j = t; j < HFCC; j += 256) {
        float z = d_zacc[b * HFCC + j] + lin1b[j];
        z = eluf(z);
        s0 += z * lin2W[j * 2 + 0];
        s1 += z * lin2W[j * 2 + 1];
    }
    __shared__ float r0[256], r1[256];
    r0[t] = s0; r1[t] = s1;
    __syncthreads();
    for (int o = 128; o > 0; o >>= 1) {
        if (t < o) { r0[t] += r0[t + o]; r1[t] += r1[t + o]; }
        __syncthreads();
    }
    if (t == 0) {
        float o0 = r0[0] + lin2b[0];
        float o1 = r1[0] + lin2b[1];
        float mx = fmaxf(o0, o1);
        float lse = mx + logf(expf(o0 - mx) + expf(o1 - mx));
        out[b * CCLS + 0] = o0 - lse;
        out[b * CCLS + 1] = o1 - lse;
    }
}

// ---------------- launcher ----------------
extern "C" void kernel_launch(void* const* d_in, const int* in_sizes, int n_in,
                              void* d_out, int out_size)
{
    const float* x     = (const float*)d_in[0];
    const int*   ei    = (const int*)d_in[2];   // int32 [2, E]
    const float* pe    = (const float*)d_in[3];
    const float* W1    = (const float*)d_in[4];
    const float* b1    = (const float*)d_in[5];
    const float* W2    = (const float*)d_in[6];
    const float* b2    = (const float*)d_in[7];
    const float* W3    = (const float*)d_in[8];
    const float* b3    = (const float*)d_in[9];
    const float* fcW   = (const float*)d_in[10];
    const float* fcb   = (const float*)d_in[11];
    const float* lin1W = (const float*)d_in[12];
    const float* lin1b = (const float*)d_in[13];
    const float* lin2W = (const float*)d_in[14];
    const float* lin2b = (const float*)d_in[15];
    float* out = (float*)d_out;

    __nv_bfloat16 *hwp, *h1p, *h2p, *ag1p, *wt1p, *wt2p, *wt3p;
    cudaGetSymbolAddress((void**)&hwp,  d_hw);
    cudaGetSymbolAddress((void**)&h1p,  d_h1);
    cudaGetSymbolAddress((void**)&h2p,  d_h2);
    cudaGetSymbolAddress((void**)&ag1p, d_ag1);
    cudaGetSymbolAddress((void**)&wt1p, d_wt1);
    cudaGetSymbolAddress((void**)&wt2p, d_wt2);
    cudaGetSymbolAddress((void**)&wt3p, d_wt3);
    int* degip; float* zaccp;
    cudaGetSymbolAddress((void**)&degip, d_degi);
    cudaGetSymbolAddress((void**)&zaccp, d_zacc);

    cudaFuncSetAttribute((void*)gemm_mma_kernel<K1PAD, true>,
                         cudaFuncAttributeMaxDynamicSharedMemorySize, GSM_BYTES);
    cudaFuncSetAttribute((void*)gemm_mma_kernel<HH, false>,
                         cudaFuncAttributeMaxDynamicSharedMemorySize, GSM_BYTES);

    // fused prep: degree count(+rank) + converts + transposes
    cudaMemsetAsync(degip, 0, NN * sizeof(int));
    prep_all_kernel<<<NB_PREP, 256>>>(ei, x, pe, W1, W2, W3);

    // CSR scan + atomic-free fill
    scan_part_kernel<<<SCANB, 1024>>>();
    scan_final_kernel<<<SCANB, 1024>>>();
    fill_csr_kernel<<<(EE + 255) / 256, 256>>>(ei);

    // layer 1: fused pre-aggregation (x + pe), then GEMM with bias+ELU -> h1
    gather_l1_kernel<<<GXB + NN, 128>>>();

    const dim3 ggrid((MM + 127) / 128, HH / 128);
    const int  agrid = (NN + 1) / 2;
    const uint4* hw4 = reinterpret_cast<const uint4*>(hwp);
    uint4* h24 = reinterpret_cast<uint4*>(h2p);

    gemm_mma_kernel<K1PAD, true><<<ggrid, 256, GSM_BYTES>>>(ag1p, wt1p, h1p, b1);

    // layer 2
    gemm_mma_kernel<HH, false><<<ggrid, 256, GSM_BYTES>>>(h1p, wt2p, hwp, nullptr);
    gather_kernel<false><<<agrid, 256>>>(hw4, b2, h24, nullptr, nullptr);

    // layer 3 (+ fused fc head -> d_g)
    gemm_mma_kernel<HH, false><<<ggrid, 256, GSM_BYTES>>>(h2p, wt3p, hwp, nullptr);
    gather_kernel<true><<<agrid, 256>>>(hw4, b3, nullptr, fcW, fcb);

    // heads
    cudaMemsetAsync(zaccp, 0, BSZ * HFCC * sizeof(float));
    lin1_kernel<<<dim3(HFCC / 128, (NN + NCH - 1) / NCH), 128>>>(lin1W);
    lin2_kernel<<<BSZ, 256>>>(lin1b, lin2W, lin2b, out);
}

// round 15
// speedup vs baseline: 1.0879x; 1.0289x over previous
#include <cuda_runtime.h>
#include <cuda_bf16.h>
#include <math.h>
#include <cstdint>

// Problem constants
#define BSZ 8
#define NN  15135
#define FF  64
#define GG  73
#define HH  256
#define HFCC 512
#define CCLS 2
#define EE  242160
#define KIN (FF + GG)        // 137
#define MM  (BSZ * NN)       // 121080
#define K1PAD 192            // layer-1 K padded to multiple of 64
#define SCANB 15             // ceil(NN/1024)

// ---------------- scratch (device globals; no dynamic alloc allowed) -------
__device__ int   d_degi[NN];
__device__ float d_dis[NN];
__device__ float d_deginv[NN];
__device__ int   d_csr_ptr[NN + 1];
__device__ int   d_rank[EE];          // per-edge rank within its dst column
__device__ int2  d_ew[EE];            // packed (src, weight-bits)
__device__ int   d_bsum[16];
__device__ __align__(16) __nv_bfloat16 d_hw[(size_t)MM * HH];
__device__ __align__(16) __nv_bfloat16 d_h1[(size_t)MM * HH];
__device__ __align__(16) __nv_bfloat16 d_h2[(size_t)MM * HH];
__device__ __align__(16) __nv_bfloat16 d_ag1[(size_t)MM * K1PAD];  // aggregated concat input
__device__ __align__(16) __nv_bfloat16 d_xb[(size_t)MM * FF];      // x in bf16
__device__ __align__(16) __nv_bfloat16 d_peb[(size_t)NN * GG];     // pe in bf16
__device__ __align__(16) __nv_bfloat16 d_wt1[HH * K1PAD];   // W1^T padded
__device__ __align__(16) __nv_bfloat16 d_wt2[HH * HH];      // W2^T
__device__ __align__(16) __nv_bfloat16 d_wt3[HH * HH];      // W3^T
__device__ float d_g[MM];
__device__ float d_zacc[BSZ * HFCC];

__device__ __forceinline__ float eluf(float v) {
    return v > 0.0f ? v : expm1f(v);
}

__device__ __forceinline__ float2 bf2f(uint32_t u) {
    __nv_bfloat162 m = *reinterpret_cast<__nv_bfloat162*>(&u);
    return make_float2(__bfloat162float(m.x), __bfloat162float(m.y));
}

// accumulate 8 bf16 lanes of u into a[0..7] with weight w
__device__ __forceinline__ void acc8(float* a, uint4 u, float w) {
    float2 m;
    m = bf2f(u.x); a[0] += w * m.x; a[1] += w * m.y;
    m = bf2f(u.y); a[2] += w * m.x; a[3] += w * m.y;
    m = bf2f(u.z); a[4] += w * m.x; a[5] += w * m.y;
    m = bf2f(u.w); a[6] += w * m.x; a[7] += w * m.y;
}

// initialize 8 lanes: a[i] = u[i] * w
__device__ __forceinline__ void set8(float* a, uint4 u, float w) {
    float2 m;
    m = bf2f(u.x); a[0] = w * m.x; a[1] = w * m.y;
    m = bf2f(u.y); a[2] = w * m.x; a[3] = w * m.y;
    m = bf2f(u.z); a[4] = w * m.x; a[5] = w * m.y;
    m = bf2f(u.w); a[6] = w * m.x; a[7] = w * m.y;
}

__device__ __forceinline__ uint4 pack8(const float* v) {
    uint4 o;
    __nv_bfloat162 p;
    p = __floats2bfloat162_rn(v[0], v[1]); o.x = *reinterpret_cast<uint32_t*>(&p);
    p = __floats2bfloat162_rn(v[2], v[3]); o.y = *reinterpret_cast<uint32_t*>(&p);
    p = __floats2bfloat162_rn(v[4], v[5]); o.z = *reinterpret_cast<uint32_t*>(&p);
    p = __floats2bfloat162_rn(v[6], v[7]); o.w = *reinterpret_cast<uint32_t*>(&p);
    return o;
}

// ---------------- fused prep: degree count(+rank) + converts + transposes --
#define XITEMS ((long long)MM * 8)
#define PEITEMS ((long long)NN * GG)
#define NB_DEG  ((EE + 255) / 256)                              // 946
#define NB_CONV ((int)((XITEMS + PEITEMS + 255) / 256))         // ~8100
#define NB_TR   (HH * 3)                                        // 768
#define NB_PREP (NB_DEG + NB_CONV + NB_TR)

__global__ __launch_bounds__(256) void prep_all_kernel(
    const int* __restrict__ ei,
    const float* __restrict__ x, const float* __restrict__ pe,
    const float* __restrict__ W1, const float* __restrict__ W2,
    const float* __restrict__ W3)
{
    const int bid = blockIdx.x;
    const int t   = threadIdx.x;
    if (bid < NB_DEG) {
        int e = bid * 256 + t;
        if (e < EE) d_rank[e] = atomicAdd(&d_degi[ei[EE + e]], 1);
    } else if (bid < NB_DEG + NB_CONV) {
        long long i = (long long)(bid - NB_DEG) * 256 + t;
        if (i < XITEMS) {
            const float4* src = reinterpret_cast<const float4*>(x) + 2 * i;
            float4 v0 = src[0], v1 = src[1];
            float v[8] = {v0.x, v0.y, v0.z, v0.w, v1.x, v1.y, v1.z, v1.w};
            reinterpret_cast<uint4*>(d_xb)[i] = pack8(v);
        } else {
            long long j = i - XITEMS;
            if (j < PEITEMS) d_peb[j] = __float2bfloat16_rn(pe[j]);
        }
    } else {
        int j = bid - NB_DEG - NB_CONV;     // 0..767
        int n = j & 255;
        int which = j >> 8;
        if (which == 0) {
            if (t < K1PAD)
                d_wt1[(size_t)n * K1PAD + t] =
                    __float2bfloat16_rn((t < KIN) ? W1[(size_t)t * HH + n] : 0.0f);
        } else {
            const float* W = (which == 1) ? W2 : W3;
            __nv_bfloat16* Wt = (which == 1) ? d_wt2 : d_wt3;
            Wt[(size_t)n * HH + t] = __float2bfloat16_rn(W[(size_t)t * HH + n]);
        }
    }
}

// ---------------- CSR scan ----------------
// stage 1: per-block local exclusive scan + block total + dis/deginv
__global__ __launch_bounds__(1024) void scan_part_kernel() {
    __shared__ int wsum[32];
    const int b = blockIdx.x, t = threadIdx.x;
    const int i = b * 1024 + t;
    const int lane = t & 31, warp = t >> 5;
    int v = 0;
    if (i < NN) {
        v = d_degi[i];
        float d = (float)v + 1.0f;
        d_dis[i]    = rsqrtf(d);
        d_deginv[i] = 1.0f / d;
    }
    int incl = v;
    #pragma unroll
    for (int o = 1; o < 32; o <<= 1) {
        int u = __shfl_up_sync(0xffffffffu, incl, o);
        if (lane >= o) incl += u;
    }
    if (lane == 31) wsum[warp] = incl;
    __syncthreads();
    if (warp == 0) {
        int s = wsum[lane];
        #pragma unroll
        for (int o = 1; o < 32; o <<= 1) {
            int u = __shfl_up_sync(0xffffffffu, s, o);
            if (lane >= o) s += u;
        }
        wsum[lane] = s;
    }
    __syncthreads();
    int wbase = (warp > 0) ? wsum[warp - 1] : 0;
    if (i < NN) d_csr_ptr[i] = wbase + incl - v;   // local exclusive
    if (t == 1023) d_bsum[b] = wsum[31];           // block total
}

// stage 2 (fused): each block re-scans the 15 block sums, adds its offset
__global__ __launch_bounds__(1024) void scan_final_kernel() {
    __shared__ int soff_sh;
    const int t = threadIdx.x;
    if (t < 32) {
        int v = (t < SCANB) ? d_bsum[t] : 0;
        int incl = v;
        #pragma unroll
        for (int o = 1; o < 32; o <<= 1) {
            int u = __shfl_up_sync(0xffffffffu, incl, o);
            if (t >= o) incl += u;
        }
        if (t == (int)blockIdx.x) soff_sh = incl - v;
        if (blockIdx.x == 0 && t == SCANB - 1) d_csr_ptr[NN] = incl;
    }
    __syncthreads();
    const int i = blockIdx.x * 1024 + t;
    if (i < NN) d_csr_ptr[i] += soff_sh;
}

// atomic-free fill: pos = csr_ptr[dst] + rank (recorded during count)
__global__ void fill_csr_kernel(const int* __restrict__ ei) {
    int e = blockIdx.x * blockDim.x + threadIdx.x;
    if (e < EE) {
        int r = ei[e];
        int c = ei[EE + e];
        int pos = d_csr_ptr[c] + d_rank[e];
        d_ew[pos] = make_int2(r, __float_as_int(d_dis[r] * d_dis[c]));
    }
}

// ---------------- layer-1 pre-aggregation (fused x + pe) -------------------
#define GXB ((NN + 1) / 2)
__global__ __launch_bounds__(128) void gather_l1_kernel() {
    const int t = threadIdx.x;
    if (blockIdx.x < GXB) {
        const int n = blockIdx.x * 2 + (t >> 6);
        if (n >= NN) return;
        const int b  = (t >> 3) & 7;
        const int fq = t & 7;
        const uint4* xp = reinterpret_cast<const uint4*>(d_xb) + (size_t)b * NN * 8;

        const int p0 = d_csr_ptr[n];
        const int p1 = d_csr_ptr[n + 1];
        // self-loop first (init accumulators; load issued before edge loop)
        float a[8];
        set8(a, __ldg(xp + (size_t)n * 8 + fq), d_deginv[n]);

        #pragma unroll 4
        for (int e = p0; e < p1; e++) {
            int2  ew = __ldg(&d_ew[e]);
            float w  = __int_as_float(ew.y);
            acc8(a, __ldg(xp + (size_t)ew.x * 8 + fq), w);
        }

        reinterpret_cast<uint4*>(d_ag1)[((size_t)b * NN + n) * 24 + fq] = pack8(a);
    } else {
        const int n = blockIdx.x - GXB;
        float a = 0.0f;
        if (t < GG) {
            const int p0 = d_csr_ptr[n];
            const int p1 = d_csr_ptr[n + 1];
            a = d_deginv[n] * __bfloat162float(__ldg(&d_peb[(size_t)n * GG + t]));
            #pragma unroll 4
            for (int e = p0; e < p1; e++) {
                int2  ew = __ldg(&d_ew[e]);
                float w  = __int_as_float(ew.y);
                a += w * __bfloat162float(__ldg(&d_peb[(size_t)ew.x * GG + t]));
            }
        }
        __nv_bfloat16 v = __float2bfloat16_rn(t < GG ? a : 0.0f);
        #pragma unroll
        for (int b = 0; b < BSZ; b++)
            d_ag1[((size_t)b * NN + n) * K1PAD + FF + t] = v;
    }
}

// ================= mma.sync bf16 GEMM with ldmatrix (R12 config) ============
__device__ __forceinline__ void cp_async16(uint32_t dst, const void* src, int sz) {
    asm volatile("cp.async.cg.shared.global [%0], [%1], 16, %2;"
                 :: "r"(dst), "l"(src), "r"(sz) : "memory");
}

__device__ __forceinline__ void mma_bf16(float* c, const uint32_t* a, const uint32_t* b) {
    asm volatile(
        "mma.sync.aligned.m16n8k16.row.col.f32.bf16.bf16.f32 "
        "{%0,%1,%2,%3}, {%4,%5,%6,%7}, {%8,%9}, {%0,%1,%2,%3};"
        : "+f"(c[0]), "+f"(c[1]), "+f"(c[2]), "+f"(c[3])
        : "r"(a[0]), "r"(a[1]), "r"(a[2]), "r"(a[3]), "r"(b[0]), "r"(b[1]));
}

__device__ __forceinline__ void ldsm_x4(uint32_t* r, uint32_t addr) {
    asm volatile("ldmatrix.sync.aligned.m8n8.x4.shared.b16 {%0,%1,%2,%3}, [%4];"
                 : "=r"(r[0]), "=r"(r[1]), "=r"(r[2]), "=r"(r[3]) : "r"(addr));
}

#define GSTRU 36
#define GBUFU (2 * 128 * GSTRU)
#define GSM_BYTES (2 * GBUFU * 4)

// EPI: fused bias + ELU epilogue (layer 1 writes h1 directly)
template <int KPAD, bool EPI>
__global__ __launch_bounds__(256, 2) void gemm_mma_kernel(
    const __nv_bfloat16* __restrict__ A, const __nv_bfloat16* __restrict__ Wt,
    __nv_bfloat16* __restrict__ hw, const float* __restrict__ bias)
{
    extern __shared__ uint32_t sm[];
    constexpr int NC = KPAD / 64;
    const int t    = threadIdx.x;
    const int lane = t & 31;
    const int wid  = t >> 5;
    const int wm   = wid >> 2;
    const int wn   = wid & 3;
    const int m0   = blockIdx.x * 128;
    const int n0   = blockIdx.y * 128;
    const int g    = lane >> 2;
    const int q    = lane & 3;

    const int mid  = lane >> 3;          // matrix id 0..3
    const int mrow = lane & 7;           // row within 8x8 matrix
    const uint32_t offA = (uint32_t)(((wm * 64 + mrow + (mid & 1) * 8) * GSTRU
                                      + (mid >> 1) * 4) * 4);
    const uint32_t offB = (uint32_t)((128 * GSTRU
                                      + (wn * 32 + (mid >> 1) * 8 + mrow) * GSTRU
                                      + (mid & 1) * 4) * 4);
    const uint32_t sbase = (uint32_t)__cvta_generic_to_shared(sm);

    float acc[4][4][4];
    #pragma unroll
    for (int mi = 0; mi < 4; mi++)
        #pragma unroll
        for (int nj = 0; nj < 4; nj++)
            #pragma unroll
            for (int r = 0; r < 4; r++) acc[mi][nj][r] = 0.0f;

    auto load_chunk = [&](int ci, int buf) {
        uint32_t* dA = sm + buf * GBUFU;
        uint32_t* dB = dA + 128 * GSTRU;
        const int k0 = ci * 64;
        #pragma unroll
        for (int r = 0; r < 4; r++) {
            int idx = t + r * 256;
            int row = idx >> 3;
            int seg = idx & 7;
            int m   = m0 + row;
            int valid = (m < MM);
            const __nv_bfloat16* srcA = A + (size_t)(valid ? m : 0) * KPAD + k0 + seg * 8;
            cp_async16((uint32_t)__cvta_generic_to_shared(dA + row * GSTRU + seg * 4),
                       srcA, valid ? 16 : 0);
            const __nv_bfloat16* srcB = Wt + (size_t)(n0 + row) * KPAD + k0 + seg * 8;
            cp_async16((uint32_t)__cvta_generic_to_shared(dB + row * GSTRU + seg * 4),
                       srcB, 16);
        }
        asm volatile("cp.async.commit_group;" ::: "memory");
    };

    load_chunk(0, 0);
    if (NC > 1) load_chunk(1, 1);
    else        asm volatile("cp.async.commit_group;" ::: "memory");

    #pragma unroll 1
    for (int i = 0; i < NC; i++) {
        asm volatile("cp.async.wait_group 1;" ::: "memory");
        __syncthreads();
        const uint32_t bufb = sbase + (uint32_t)((i & 1) * GBUFU * 4);
        const uint32_t aA = bufb + offA;
        const uint32_t aB = bufb + offB;

        #pragma unroll
        for (int ks = 0; ks < 4; ks++) {
            const uint32_t kso = (uint32_t)(ks * 32);
            uint32_t a[4][4], b[4][2];
            #pragma unroll
            for (int mi = 0; mi < 4; mi++)
                ldsm_x4(a[mi], aA + (uint32_t)(mi * 16 * GSTRU * 4) + kso);
            {
                uint32_t r0[4], r1[4];
                ldsm_x4(r0, aB + kso);
                ldsm_x4(r1, aB + (uint32_t)(16 * GSTRU * 4) + kso);
                b[0][0] = r0[0]; b[0][1] = r0[1]; b[1][0] = r0[2]; b[1][1] = r0[3];
                b[2][0] = r1[0]; b[2][1] = r1[1]; b[3][0] = r1[2]; b[3][1] = r1[3];
            }
            #pragma unroll
            for (int mi = 0; mi < 4; mi++)
                #pragma unroll
                for (int nj = 0; nj < 4; nj++)
                    mma_bf16(acc[mi][nj], a[mi], b[nj]);
        }
        __syncthreads();
        if (i + 2 < NC) load_chunk(i + 2, i & 1);
        else            asm volatile("cp.async.commit_group;" ::: "memory");
    }

    __nv_bfloat162* hw2 = reinterpret_cast<__nv_bfloat162*>(hw);
    #pragma unroll
    for (int mi = 0; mi < 4; mi++) {
        int r = m0 + wm * 64 + mi * 16 + g;
        #pragma unroll
        for (int nj = 0; nj < 4; nj++) {
            int c  = n0 + wn * 32 + nj * 8 + q * 2;
            float v0 = acc[mi][nj][0], v1 = acc[mi][nj][1];
            float v2 = acc[mi][nj][2], v3 = acc[mi][nj][3];
            if (EPI) {
                float2 bv = *reinterpret_cast<const float2*>(bias + c);
                v0 = eluf(v0 + bv.x); v1 = eluf(v1 + bv.y);
                v2 = eluf(v2 + bv.x); v3 = eluf(v3 + bv.y);
            }
            int c2 = c >> 1;
            if (r < MM)
                hw2[(size_t)r * 128 + c2] = __floats2bfloat162_rn(v0, v1);
            if (r + 8 < MM)
                hw2[(size_t)(r + 8) * 128 + c2] = __floats2bfloat162_rn(v2, v3);
        }
    }
}

// ---------------- CSR gather (layers 2/3): 1 node / 128 thr (R12 config) ----
template <bool FUSE_FC>
__global__ __launch_bounds__(128) void gather_kernel(
    const uint4* __restrict__ hw4, const float* __restrict__ bias,
    uint4* __restrict__ hout4,
    const float* __restrict__ fcW, const float* __restrict__ fcb)
{
    const int n  = blockIdx.x;
    const int t  = threadIdx.x;
    const int fq = t & 31;
    const int bp = t >> 5;
    const int b0 = 2 * bp, b1 = 2 * bp + 1;
    const size_t plane = (size_t)NN * 32;
    const uint4* hp0 = hw4 + (size_t)b0 * plane;
    const uint4* hp1 = hw4 + (size_t)b1 * plane;

    __shared__ float sfw[FUSE_FC ? 768 : 1];
    if (FUSE_FC) {
        #pragma unroll
        for (int i = t; i < 768; i += 128) sfw[i] = fcW[i];
        __syncthreads();
    }

    const int p0 = d_csr_ptr[n];
    const int p1 = d_csr_ptr[n + 1];
    const float di = d_deginv[n];
    const size_t so = (size_t)n * 32 + fq;

    // self-loop first: loads issued before edge loop, latency hidden behind it
    float a0[8], a1v[8];
    set8(a0,  __ldg(hp0 + so), di);
    set8(a1v, __ldg(hp1 + so), di);

    #pragma unroll 4
    for (int e = p0; e < p1; e++) {
        int2  ew = __ldg(&d_ew[e]);
        float w  = __int_as_float(ew.y);
        size_t ro = (size_t)ew.x * 32 + fq;
        uint4 u0 = __ldg(hp0 + ro);
        uint4 u1 = __ldg(hp1 + ro);
        acc8(a0,  u0, w);
        acc8(a1v, u1, w);
    }

    const float4 bsa = reinterpret_cast<const float4*>(bias)[2 * fq];
    const float4 bsb = reinterpret_cast<const float4*>(bias)[2 * fq + 1];
    const float bs[8] = {bsa.x, bsa.y, bsa.z, bsa.w, bsb.x, bsb.y, bsb.z, bsb.w};

    float v0[8], v1[8];
    #pragma unroll
    for (int i = 0; i < 8; i++) {
        v0[i] = eluf(a0[i]  + bs[i]);
        v1[i] = eluf(a1v[i] + bs[i]);
    }

    if (!FUSE_FC) {
        hout4[(size_t)b0 * plane + so] = pack8(v0);
        hout4[(size_t)b1 * plane + so] = pack8(v1);
    } else {
        const uint4* h1p0 = reinterpret_cast<const uint4*>(d_h1) + (size_t)b0 * plane;
        const uint4* h1p1 = reinterpret_cast<const uint4*>(d_h1) + (size_t)b1 * plane;
        const uint4* h2p0 = reinterpret_cast<const uint4*>(d_h2) + (size_t)b0 * plane;
        const uint4* h2p1 = reinterpret_cast<const uint4*>(d_h2) + (size_t)b1 * plane;
        float h10[8], h11[8], h20[8], h21[8];
        set8(h10, __ldg(h1p0 + so), 1.0f); set8(h11, __ldg(h1p1 + so), 1.0f);
        set8(h20, __ldg(h2p0 + so), 1.0f); set8(h21, __ldg(h2p1 + so), 1.0f);
        float g0 = 0.0f, g1 = 0.0f;
        #pragma unroll
        for (int i = 0; i < 8; i++) {
            const float* fw = &sfw[24 * fq + 3 * i];
            g0 += h10[i] * fw[0] + h20[i] * fw[1] + v0[i] * fw[2];
            g1 += h11[i] * fw[0] + h21[i] * fw[1] + v1[i] * fw[2];
        }
        #pragma unroll
        for (int o = 16; o > 0; o >>= 1) {
            g0 += __shfl_down_sync(0xffffffffu, g0, o);
            g1 += __shfl_down_sync(0xffffffffu, g1, o);
        }
        if (fq == 0) {
            float fb = fcb[0];
            d_g[(size_t)b0 * NN + n] = g0 + fb;
            d_g[(size_t)b1 * NN + n] = g1 + fb;
        }
    }
}

// ---------------- lin1: g[b,N] @ lin1_W[N,512] (accumulate) ----------------
#define NCH 256
__global__ __launch_bounds__(128) void lin1_kernel(const float* __restrict__ W)
{
    __shared__ float gs[BSZ][NCH];
    const int j  = blockIdx.x * 128 + threadIdx.x;
    const int n0 = blockIdx.y * NCH;
    const int cn = min(NCH, NN - n0);
    for (int idx = threadIdx.x; idx < BSZ * NCH; idx += 128) {
        int b  = idx >> 8;
        int nl = idx & (NCH - 1);
        gs[b][nl] = (nl < cn) ? d_g[(size_t)b * NN + n0 + nl] : 0.0f;
    }
    __syncthreads();
    float acc[BSZ];
    #pragma unroll
    for (int b = 0; b < BSZ; b++) acc[b] = 0.0f;
    for (int nl = 0; nl < cn; nl++) {
        float w = W[(size_t)(n0 + nl) * HFCC + j];
        #pragma unroll
        for (int b = 0; b < BSZ; b++) acc[b] += gs[b][nl] * w;
    }
    #pragma unroll
    for (int b = 0; b < BSZ; b++) atomicAdd(&d_zacc[b * HFCC + j], acc[b]);
}

// ---------------- lin2 + log_softmax ----------------
__global__ __launch_bounds__(256) void lin2_kernel(
    const float* __restrict__ lin1b, const float* __restrict__ lin2W,
    const float* __restrict__ lin2b, float* __restrict__ out)
{
    const int b = blockIdx.x;
    const int t = threadIdx.x;
    float s0 = 0.0f, s1 = 0.0f;
    for (int j = t; j < HFCC; j += 256) {
        float z = d_zacc[b * HFCC + j] + lin1b[j];
        z = eluf(z);
        s0 += z * lin2W[j * 2 + 0];
        s1 += z * lin2W[j * 2 + 1];
    }
    __shared__ float r0[256], r1[256];
    r0[t] = s0; r1[t] = s1;
    __syncthreads();
    for (int o = 128; o > 0; o >>= 1) {
        if (t < o) { r0[t] += r0[t + o]; r1[t] += r1[t + o]; }
        __syncthreads();
    }
    if (t == 0) {
        float o0 = r0[0] + lin2b[0];
        float o1 = r1[0] + lin2b[1];
        float mx = fmaxf(o0, o1);
        float lse = mx + logf(expf(o0 - mx) + expf(o1 - mx));
        out[b * CCLS + 0] = o0 - lse;
        out[b * CCLS + 1] = o1 - lse;
    }
}

// ---------------- launcher ----------------
extern "C" void kernel_launch(void* const* d_in, const int* in_sizes, int n_in,
                              void* d_out, int out_size)
{
    const float* x     = (const float*)d_in[0];
    const int*   ei    = (const int*)d_in[2];   // int32 [2, E]
    const float* pe    = (const float*)d_in[3];
    const float* W1    = (const float*)d_in[4];
    const float* b1    = (const float*)d_in[5];
    const float* W2    = (const float*)d_in[6];
    const float* b2    = (const float*)d_in[7];
    const float* W3    = (const float*)d_in[8];
    const float* b3    = (const float*)d_in[9];
    const float* fcW   = (const float*)d_in[10];
    const float* fcb   = (const float*)d_in[11];
    const float* lin1W = (const float*)d_in[12];
    const float* lin1b = (const float*)d_in[13];
    const float* lin2W = (const float*)d_in[14];
    const float* lin2b = (const float*)d_in[15];
    float* out = (float*)d_out;

    __nv_bfloat16 *hwp, *h1p, *h2p, *ag1p, *wt1p, *wt2p, *wt3p;
    cudaGetSymbolAddress((void**)&hwp,  d_hw);
    cudaGetSymbolAddress((void**)&h1p,  d_h1);
    cudaGetSymbolAddress((void**)&h2p,  d_h2);
    cudaGetSymbolAddress((void**)&ag1p, d_ag1);
    cudaGetSymbolAddress((void**)&wt1p, d_wt1);
    cudaGetSymbolAddress((void**)&wt2p, d_wt2);
    cudaGetSymbolAddress((void**)&wt3p, d_wt3);
    int* degip; float* zaccp;
    cudaGetSymbolAddress((void**)&degip, d_degi);
    cudaGetSymbolAddress((void**)&zaccp, d_zacc);

    cudaFuncSetAttribute((void*)gemm_mma_kernel<K1PAD, true>,
                         cudaFuncAttributeMaxDynamicSharedMemorySize, GSM_BYTES);
    cudaFuncSetAttribute((void*)gemm_mma_kernel<HH, false>,
                         cudaFuncAttributeMaxDynamicSharedMemorySize, GSM_BYTES);

    // fused prep: degree count(+rank) + converts + transposes
    cudaMemsetAsync(degip, 0, NN * sizeof(int));
    prep_all_kernel<<<NB_PREP, 256>>>(ei, x, pe, W1, W2, W3);

    // CSR scan + atomic-free fill
    scan_part_kernel<<<SCANB, 1024>>>();
    scan_final_kernel<<<SCANB, 1024>>>();
    fill_csr_kernel<<<(EE + 255) / 256, 256>>>(ei);

    // layer 1: fused pre-aggregation (x + pe), then GEMM with bias+ELU -> h1
    gather_l1_kernel<<<GXB + NN, 128>>>();

    const dim3 ggrid((MM + 127) / 128, HH / 128);
    const uint4* hw4 = reinterpret_cast<const uint4*>(hwp);
    uint4* h24 = reinterpret_cast<uint4*>(h2p);

    gemm_mma_kernel<K1PAD, true><<<ggrid, 256, GSM_BYTES>>>(ag1p, wt1p, h1p, b1);

    // layer 2
    gemm_mma_kernel<HH, false><<<ggrid, 256, GSM_BYTES>>>(h1p, wt2p, hwp, nullptr);
    gather_kernel<false><<<NN, 128>>>(hw4, b2, h24, nullptr, nullptr);

    // layer 3 (+ fused fc head -> d_g)
    gemm_mma_kernel<HH, false><<<ggrid, 256, GSM_BYTES>>>(h2p, wt3p, hwp, nullptr);
    gather_kernel<true><<<NN, 128>>>(hw4, b3, nullptr, fcW, fcb);

    // heads
    cudaMemsetAsync(zaccp, 0, BSZ * HFCC * sizeof(float));
    lin1_kernel<<<dim3(HFCC / 128, (NN + NCH - 1) / NCH), 128>>>(lin1W);
    lin2_kernel<<<BSZ, 256>>>(lin1b, lin2W, lin2b, out);
}

// round 16
// speedup vs baseline: 1.0975x; 1.0088x over previous
#include <cuda_runtime.h>
#include <cuda_bf16.h>
#include <math.h>
#include <cstdint>

// Problem constants
#define BSZ 8
#define NN  15135
#define FF  64
#define GG  73
#define HH  256
#define HFCC 512
#define CCLS 2
#define EE  242160
#define KIN (FF + GG)        // 137
#define MM  (BSZ * NN)       // 121080
#define K1PAD 192            // layer-1 K padded to multiple of 64
#define SCANB 15             // ceil(NN/1024)

// ---------------- scratch (device globals; no dynamic alloc allowed) -------
__device__ int   d_degi[NN];
__device__ float d_dis[NN];
__device__ float d_deginv[NN];
__device__ int   d_csr_ptr[NN + 1];
__device__ int   d_rank[EE];          // per-edge rank within its dst column
__device__ int2  d_ew[EE];            // packed (src, weight-bits)
__device__ int   d_bsum[16];
__device__ __align__(16) __nv_bfloat16 d_hw[(size_t)MM * HH];
__device__ __align__(16) __nv_bfloat16 d_h1[(size_t)MM * HH];
__device__ __align__(16) __nv_bfloat16 d_h2[(size_t)MM * HH];
__device__ __align__(16) __nv_bfloat16 d_ag1[(size_t)MM * K1PAD];  // aggregated concat input
__device__ __align__(16) __nv_bfloat16 d_xb[(size_t)MM * FF];      // x in bf16
__device__ __align__(16) __nv_bfloat16 d_peb[(size_t)NN * GG];     // pe in bf16
__device__ __align__(16) __nv_bfloat16 d_wt1[HH * K1PAD];   // W1^T padded
__device__ __align__(16) __nv_bfloat16 d_wt2[HH * HH];      // W2^T
__device__ __align__(16) __nv_bfloat16 d_wt3[HH * HH];      // W3^T
__device__ float d_g[MM];
__device__ float d_zacc[BSZ * HFCC];

__device__ __forceinline__ float eluf(float v) {
    return v > 0.0f ? v : expm1f(v);
}

__device__ __forceinline__ float2 bf2f(uint32_t u) {
    __nv_bfloat162 m = *reinterpret_cast<__nv_bfloat162*>(&u);
    return make_float2(__bfloat162float(m.x), __bfloat162float(m.y));
}

// accumulate 8 bf16 lanes of u into a[0..7] with weight w
__device__ __forceinline__ void acc8(float* a, uint4 u, float w) {
    float2 m;
    m = bf2f(u.x); a[0] += w * m.x; a[1] += w * m.y;
    m = bf2f(u.y); a[2] += w * m.x; a[3] += w * m.y;
    m = bf2f(u.z); a[4] += w * m.x; a[5] += w * m.y;
    m = bf2f(u.w); a[6] += w * m.x; a[7] += w * m.y;
}

// initialize 8 lanes: a[i] = u[i] * w
__device__ __forceinline__ void set8(float* a, uint4 u, float w) {
    float2 m;
    m = bf2f(u.x); a[0] = w * m.x; a[1] = w * m.y;
    m = bf2f(u.y); a[2] = w * m.x; a[3] = w * m.y;
    m = bf2f(u.z); a[4] = w * m.x; a[5] = w * m.y;
    m = bf2f(u.w); a[6] = w * m.x; a[7] = w * m.y;
}

__device__ __forceinline__ uint4 pack8(const float* v) {
    uint4 o;
    __nv_bfloat162 p;
    p = __floats2bfloat162_rn(v[0], v[1]); o.x = *reinterpret_cast<uint32_t*>(&p);
    p = __floats2bfloat162_rn(v[2], v[3]); o.y = *reinterpret_cast<uint32_t*>(&p);
    p = __floats2bfloat162_rn(v[4], v[5]); o.z = *reinterpret_cast<uint32_t*>(&p);
    p = __floats2bfloat162_rn(v[6], v[7]); o.w = *reinterpret_cast<uint32_t*>(&p);
    return o;
}

// ---------------- fused prep: degree count(+rank) + converts + transposes --
#define XITEMS ((long long)MM * 8)
#define PEITEMS ((long long)NN * GG)
#define NB_DEG  ((EE + 255) / 256)                              // 946
#define NB_CONV ((int)((XITEMS + PEITEMS + 255) / 256))         // ~8100
#define NB_TR   (HH * 3)                                        // 768
#define NB_PREP (NB_DEG + NB_CONV + NB_TR)

__global__ __launch_bounds__(256) void prep_all_kernel(
    const int* __restrict__ ei,
    const float* __restrict__ x, const float* __restrict__ pe,
    const float* __restrict__ W1, const float* __restrict__ W2,
    const float* __restrict__ W3)
{
    const int bid = blockIdx.x;
    const int t   = threadIdx.x;
    if (bid < NB_DEG) {
        int e = bid * 256 + t;
        if (e < EE) d_rank[e] = atomicAdd(&d_degi[ei[EE + e]], 1);
    } else if (bid < NB_DEG + NB_CONV) {
        long long i = (long long)(bid - NB_DEG) * 256 + t;
        if (i < XITEMS) {
            const float4* src = reinterpret_cast<const float4*>(x) + 2 * i;
            float4 v0 = src[0], v1 = src[1];
            float v[8] = {v0.x, v0.y, v0.z, v0.w, v1.x, v1.y, v1.z, v1.w};
            reinterpret_cast<uint4*>(d_xb)[i] = pack8(v);
        } else {
            long long j = i - XITEMS;
            if (j < PEITEMS) d_peb[j] = __float2bfloat16_rn(pe[j]);
        }
    } else {
        int j = bid - NB_DEG - NB_CONV;     // 0..767
        int n = j & 255;
        int which = j >> 8;
        if (which == 0) {
            if (t < K1PAD)
                d_wt1[(size_t)n * K1PAD + t] =
                    __float2bfloat16_rn((t < KIN) ? W1[(size_t)t * HH + n] : 0.0f);
        } else {
            const float* W = (which == 1) ? W2 : W3;
            __nv_bfloat16* Wt = (which == 1) ? d_wt2 : d_wt3;
            Wt[(size_t)n * HH + t] = __float2bfloat16_rn(W[(size_t)t * HH + n]);
        }
    }
}

// ---------------- CSR scan ----------------
// stage 1: per-block local exclusive scan + block total + dis/deginv
__global__ __launch_bounds__(1024) void scan_part_kernel() {
    __shared__ int wsum[32];
    const int b = blockIdx.x, t = threadIdx.x;
    const int i = b * 1024 + t;
    const int lane = t & 31, warp = t >> 5;
    int v = 0;
    if (i < NN) {
        v = d_degi[i];
        float d = (float)v + 1.0f;
        d_dis[i]    = rsqrtf(d);
        d_deginv[i] = 1.0f / d;
    }
    int incl = v;
    #pragma unroll
    for (int o = 1; o < 32; o <<= 1) {
        int u = __shfl_up_sync(0xffffffffu, incl, o);
        if (lane >= o) incl += u;
    }
    if (lane == 31) wsum[warp] = incl;
    __syncthreads();
    if (warp == 0) {
        int s = wsum[lane];
        #pragma unroll
        for (int o = 1; o < 32; o <<= 1) {
            int u = __shfl_up_sync(0xffffffffu, s, o);
            if (lane >= o) s += u;
        }
        wsum[lane] = s;
    }
    __syncthreads();
    int wbase = (warp > 0) ? wsum[warp - 1] : 0;
    if (i < NN) d_csr_ptr[i] = wbase + incl - v;   // local exclusive
    if (t == 1023) d_bsum[b] = wsum[31];           // block total
}

// stage 2 (fused): each block re-scans the 15 block sums, adds its offset
__global__ __launch_bounds__(1024) void scan_final_kernel() {
    __shared__ int soff_sh;
    const int t = threadIdx.x;
    if (t < 32) {
        int v = (t < SCANB) ? d_bsum[t] : 0;
        int incl = v;
        #pragma unroll
        for (int o = 1; o < 32; o <<= 1) {
            int u = __shfl_up_sync(0xffffffffu, incl, o);
            if (t >= o) incl += u;
        }
        if (t == (int)blockIdx.x) soff_sh = incl - v;
        if (blockIdx.x == 0 && t == SCANB - 1) d_csr_ptr[NN] = incl;
    }
    __syncthreads();
    const int i = blockIdx.x * 1024 + t;
    if (i < NN) d_csr_ptr[i] += soff_sh;
}

// atomic-free fill: pos = csr_ptr[dst] + rank (recorded during count)
__global__ void fill_csr_kernel(const int* __restrict__ ei) {
    int e = blockIdx.x * blockDim.x + threadIdx.x;
    if (e < EE) {
        int r = ei[e];
        int c = ei[EE + e];
        int pos = d_csr_ptr[c] + d_rank[e];
        d_ew[pos] = make_int2(r, __float_as_int(d_dis[r] * d_dis[c]));
    }
}

// ---------------- layer-1 pre-aggregation (fused x + pe) -------------------
#define GXB ((NN + 1) / 2)
__global__ __launch_bounds__(128) void gather_l1_kernel() {
    const int t = threadIdx.x;
    if (blockIdx.x < GXB) {
        const int n = blockIdx.x * 2 + (t >> 6);
        if (n >= NN) return;
        const int b  = (t >> 3) & 7;
        const int fq = t & 7;
        const uint4* xp = reinterpret_cast<const uint4*>(d_xb) + (size_t)b * NN * 8;

        const int p0 = d_csr_ptr[n];
        const int p1 = d_csr_ptr[n + 1];
        // self-loop first (init accumulators; load issued before edge loop)
        float a[8];
        set8(a, __ldg(xp + (size_t)n * 8 + fq), d_deginv[n]);

        #pragma unroll 8
        for (int e = p0; e < p1; e++) {
            int2  ew = __ldg(&d_ew[e]);
            float w  = __int_as_float(ew.y);
            acc8(a, __ldg(xp + (size_t)ew.x * 8 + fq), w);
        }

        reinterpret_cast<uint4*>(d_ag1)[((size_t)b * NN + n) * 24 + fq] = pack8(a);
    } else {
        const int n = blockIdx.x - GXB;
        float a = 0.0f;
        if (t < GG) {
            const int p0 = d_csr_ptr[n];
            const int p1 = d_csr_ptr[n + 1];
            a = d_deginv[n] * __bfloat162float(__ldg(&d_peb[(size_t)n * GG + t]));
            #pragma unroll 8
            for (int e = p0; e < p1; e++) {
                int2  ew = __ldg(&d_ew[e]);
                float w  = __int_as_float(ew.y);
                a += w * __bfloat162float(__ldg(&d_peb[(size_t)ew.x * GG + t]));
            }
        }
        __nv_bfloat16 v = __float2bfloat16_rn(t < GG ? a : 0.0f);
        #pragma unroll
        for (int b = 0; b < BSZ; b++)
            d_ag1[((size_t)b * NN + n) * K1PAD + FF + t] = v;
    }
}

// ================= mma.sync bf16 GEMM with ldmatrix (R12 config) ============
__device__ __forceinline__ void cp_async16(uint32_t dst, const void* src, int sz) {
    asm volatile("cp.async.cg.shared.global [%0], [%1], 16, %2;"
                 :: "r"(dst), "l"(src), "r"(sz) : "memory");
}

__device__ __forceinline__ void mma_bf16(float* c, const uint32_t* a, const uint32_t* b) {
    asm volatile(
        "mma.sync.aligned.m16n8k16.row.col.f32.bf16.bf16.f32 "
        "{%0,%1,%2,%3}, {%4,%5,%6,%7}, {%8,%9}, {%0,%1,%2,%3};"
        : "+f"(c[0]), "+f"(c[1]), "+f"(c[2]), "+f"(c[3])
        : "r"(a[0]), "r"(a[1]), "r"(a[2]), "r"(a[3]), "r"(b[0]), "r"(b[1]));
}

__device__ __forceinline__ void ldsm_x4(uint32_t* r, uint32_t addr) {
    asm volatile("ldmatrix.sync.aligned.m8n8.x4.shared.b16 {%0,%1,%2,%3}, [%4];"
                 : "=r"(r[0]), "=r"(r[1]), "=r"(r[2]), "=r"(r[3]) : "r"(addr));
}

#define GSTRU 36
#define GBUFU (2 * 128 * GSTRU)
#define GSM_BYTES (2 * GBUFU * 4)

// EPI: fused bias + ELU epilogue (layer 1 writes h1 directly)
template <int KPAD, bool EPI>
__global__ __launch_bounds__(256, 2) void gemm_mma_kernel(
    const __nv_bfloat16* __restrict__ A, const __nv_bfloat16* __restrict__ Wt,
    __nv_bfloat16* __restrict__ hw, const float* __restrict__ bias)
{
    extern __shared__ uint32_t sm[];
    constexpr int NC = KPAD / 64;
    const int t    = threadIdx.x;
    const int lane = t & 31;
    const int wid  = t >> 5;
    const int wm   = wid >> 2;
    const int wn   = wid & 3;
    const int m0   = blockIdx.x * 128;
    const int n0   = blockIdx.y * 128;
    const int g    = lane >> 2;
    const int q    = lane & 3;

    const int mid  = lane >> 3;          // matrix id 0..3
    const int mrow = lane & 7;           // row within 8x8 matrix
    const uint32_t offA = (uint32_t)(((wm * 64 + mrow + (mid & 1) * 8) * GSTRU
                                      + (mid >> 1) * 4) * 4);
    const uint32_t offB = (uint32_t)((128 * GSTRU
                                      + (wn * 32 + (mid >> 1) * 8 + mrow) * GSTRU
                                      + (mid & 1) * 4) * 4);
    const uint32_t sbase = (uint32_t)__cvta_generic_to_shared(sm);

    float acc[4][4][4];
    #pragma unroll
    for (int mi = 0; mi < 4; mi++)
        #pragma unroll
        for (int nj = 0; nj < 4; nj++)
            #pragma unroll
            for (int r = 0; r < 4; r++) acc[mi][nj][r] = 0.0f;

    auto load_chunk = [&](int ci, int buf) {
        uint32_t* dA = sm + buf * GBUFU;
        uint32_t* dB = dA + 128 * GSTRU;
        const int k0 = ci * 64;
        #pragma unroll
        for (int r = 0; r < 4; r++) {
            int idx = t + r * 256;
            int row = idx >> 3;
            int seg = idx & 7;
            int m   = m0 + row;
            int valid = (m < MM);
            const __nv_bfloat16* srcA = A + (size_t)(valid ? m : 0) * KPAD + k0 + seg * 8;
            cp_async16((uint32_t)__cvta_generic_to_shared(dA + row * GSTRU + seg * 4),
                       srcA, valid ? 16 : 0);
            const __nv_bfloat16* srcB = Wt + (size_t)(n0 + row) * KPAD + k0 + seg * 8;
            cp_async16((uint32_t)__cvta_generic_to_shared(dB + row * GSTRU + seg * 4),
                       srcB, 16);
        }
        asm volatile("cp.async.commit_group;" ::: "memory");
    };

    load_chunk(0, 0);
    if (NC > 1) load_chunk(1, 1);
    else        asm volatile("cp.async.commit_group;" ::: "memory");

    #pragma unroll 1
    for (int i = 0; i < NC; i++) {
        asm volatile("cp.async.wait_group 1;" ::: "memory");
        __syncthreads();
        const uint32_t bufb = sbase + (uint32_t)((i & 1) * GBUFU * 4);
        const uint32_t aA = bufb + offA;
        const uint32_t aB = bufb + offB;

        #pragma unroll
        for (int ks = 0; ks < 4; ks++) {
            const uint32_t kso = (uint32_t)(ks * 32);
            uint32_t a[4][4], b[4][2];
            #pragma unroll
            for (int mi = 0; mi < 4; mi++)
                ldsm_x4(a[mi], aA + (uint32_t)(mi * 16 * GSTRU * 4) + kso);
            {
                uint32_t r0[4], r1[4];
                ldsm_x4(r0, aB + kso);
                ldsm_x4(r1, aB + (uint32_t)(16 * GSTRU * 4) + kso);
                b[0][0] = r0[0]; b[0][1] = r0[1]; b[1][0] = r0[2]; b[1][1] = r0[3];
                b[2][0] = r1[0]; b[2][1] = r1[1]; b[3][0] = r1[2]; b[3][1] = r1[3];
            }
            #pragma unroll
            for (int mi = 0; mi < 4; mi++)
                #pragma unroll
                for (int nj = 0; nj < 4; nj++)
                    mma_bf16(acc[mi][nj], a[mi], b[nj]);
        }
        __syncthreads();
        if (i + 2 < NC) load_chunk(i + 2, i & 1);
        else            asm volatile("cp.async.commit_group;" ::: "memory");
    }

    __nv_bfloat162* hw2 = reinterpret_cast<__nv_bfloat162*>(hw);
    #pragma unroll
    for (int mi = 0; mi < 4; mi++) {
        int r = m0 + wm * 64 + mi * 16 + g;
        #pragma unroll
        for (int nj = 0; nj < 4; nj++) {
            int c  = n0 + wn * 32 + nj * 8 + q * 2;
            float v0 = acc[mi][nj][0], v1 = acc[mi][nj][1];
            float v2 = acc[mi][nj][2], v3 = acc[mi][nj][3];
            if (EPI) {
                float2 bv = *reinterpret_cast<const float2*>(bias + c);
                v0 = eluf(v0 + bv.x); v1 = eluf(v1 + bv.y);
                v2 = eluf(v2 + bv.x); v3 = eluf(v3 + bv.y);
            }
            int c2 = c >> 1;
            if (r < MM)
                hw2[(size_t)r * 128 + c2] = __floats2bfloat162_rn(v0, v1);
            if (r + 8 < MM)
                hw2[(size_t)(r + 8) * 128 + c2] = __floats2bfloat162_rn(v2, v3);
        }
    }
}

// ---------------- CSR gather (layers 2/3): 1 node / 128 thr -----------------
template <bool FUSE_FC>
__global__ __launch_bounds__(128) void gather_kernel(
    const uint4* __restrict__ hw4, const float* __restrict__ bias,
    uint4* __restrict__ hout4,
    const float* __restrict__ fcW, const float* __restrict__ fcb)
{
    const int n  = blockIdx.x;
    const int t  = threadIdx.x;
    const int fq = t & 31;
    const int bp = t >> 5;
    const int b0 = 2 * bp, b1 = 2 * bp + 1;
    const size_t plane = (size_t)NN * 32;
    const uint4* hp0 = hw4 + (size_t)b0 * plane;
    const uint4* hp1 = hw4 + (size_t)b1 * plane;

    __shared__ float sfw[FUSE_FC ? 768 : 1];
    if (FUSE_FC) {
        #pragma unroll
        for (int i = t; i < 768; i += 128) sfw[i] = fcW[i];
        __syncthreads();
    }

    const int p0 = d_csr_ptr[n];
    const int p1 = d_csr_ptr[n + 1];
    const float di = d_deginv[n];
    const size_t so = (size_t)n * 32 + fq;

    // self-loop first: loads issued before edge loop, latency hidden behind it
    float a0[8], a1v[8];
    set8(a0,  __ldg(hp0 + so), di);
    set8(a1v, __ldg(hp1 + so), di);

    #pragma unroll 8
    for (int e = p0; e < p1; e++) {
        int2  ew = __ldg(&d_ew[e]);
        float w  = __int_as_float(ew.y);
        size_t ro = (size_t)ew.x * 32 + fq;
        uint4 u0 = __ldg(hp0 + ro);
        uint4 u1 = __ldg(hp1 + ro);
        acc8(a0,  u0, w);
        acc8(a1v, u1, w);
    }

    const float4 bsa = reinterpret_cast<const float4*>(bias)[2 * fq];
    const float4 bsb = reinterpret_cast<const float4*>(bias)[2 * fq + 1];
    const float bs[8] = {bsa.x, bsa.y, bsa.z, bsa.w, bsb.x, bsb.y, bsb.z, bsb.w};

    float v0[8], v1[8];
    #pragma unroll
    for (int i = 0; i < 8; i++) {
        v0[i] = eluf(a0[i]  + bs[i]);
        v1[i] = eluf(a1v[i] + bs[i]);
    }

    if (!FUSE_FC) {
        hout4[(size_t)b0 * plane + so] = pack8(v0);
        hout4[(size_t)b1 * plane + so] = pack8(v1);
    } else {
        const uint4* h1p0 = reinterpret_cast<const uint4*>(d_h1) + (size_t)b0 * plane;
        const uint4* h1p1 = reinterpret_cast<const uint4*>(d_h1) + (size_t)b1 * plane;
        const uint4* h2p0 = reinterpret_cast<const uint4*>(d_h2) + (size_t)b0 * plane;
        const uint4* h2p1 = reinterpret_cast<const uint4*>(d_h2) + (size_t)b1 * plane;
        float h10[8], h11[8], h20[8], h21[8];
        set8(h10, __ldg(h1p0 + so), 1.0f); set8(h11, __ldg(h1p1 + so), 1.0f);
        set8(h20, __ldg(h2p0 + so), 1.0f); set8(h21, __ldg(h2p1 + so), 1.0f);
        float g0 = 0.0f, g1 = 0.0f;
        #pragma unroll
        for (int i = 0; i < 8; i++) {
            const float* fw = &sfw[24 * fq + 3 * i];
            g0 += h10[i] * fw[0] + h20[i] * fw[1] + v0[i] * fw[2];
            g1 += h11[i] * fw[0] + h21[i] * fw[1] + v1[i] * fw[2];
        }
        #pragma unroll
        for (int o = 16; o > 0; o >>= 1) {
            g0 += __shfl_down_sync(0xffffffffu, g0, o);
            g1 += __shfl_down_sync(0xffffffffu, g1, o);
        }
        if (fq == 0) {
            float fb = fcb[0];
            d_g[(size_t)b0 * NN + n] = g0 + fb;
            d_g[(size_t)b1 * NN + n] = g1 + fb;
        }
    }
}

// ---------------- lin1: g[b,N] @ lin1_W[N,512] (accumulate) ----------------
#define NCH 256
__global__ __launch_bounds__(128) void lin1_kernel(const float* __restrict__ W)
{
    __shared__ float gs[BSZ][NCH];
    const int j  = blockIdx.x * 128 + threadIdx.x;
    const int n0 = blockIdx.y * NCH;
    const int cn = min(NCH, NN - n0);
    for (int idx = threadIdx.x; idx < BSZ * NCH; idx += 128) {
        int b  = idx >> 8;
        int nl = idx & (NCH - 1);
        gs[b][nl] = (nl < cn) ? d_g[(size_t)b * NN + n0 + nl] : 0.0f;
    }
    __syncthreads();
    float acc[BSZ];
    #pragma unroll
    for (int b = 0; b < BSZ; b++) acc[b] = 0.0f;
    for (int nl = 0; nl < cn; nl++) {
        float w = W[(size_t)(n0 + nl) * HFCC + j];
        #pragma unroll
        for (int b = 0; b < BSZ; b++) acc[b] += gs[b][nl] * w;
    }
    #pragma unroll
    for (int b = 0; b < BSZ; b++) atomicAdd(&d_zacc[b * HFCC + j], acc[b]);
}

// ---------------- lin2 + log_softmax ----------------
__global__ __launch_bounds__(256) void lin2_kernel(
    const float* __restrict__ lin1b, const float* __restrict__ lin2W,
    const float* __restrict__ lin2b, float* __restrict__ out)
{
    const int b = blockIdx.x;
    const int t = threadIdx.x;
    float s0 = 0.0f, s1 = 0.0f;
    for (int j = t; j < HFCC; j += 256) {
        float z = d_zacc[b * HFCC + j] + lin1b[j];
        z = eluf(z);
        s0 += z * lin2W[j * 2 + 0];
        s1 += z * lin2W[j * 2 + 1];
    }
    __shared__ float r0[256], r1[256];
    r0[t] = s0; r1[t] = s1;
    __syncthreads();
    for (int o = 128; o > 0; o >>= 1) {
        if (t < o) { r0[t] += r0[t + o]; r1[t] += r1[t + o]; }
        __syncthreads();
    }
    if (t == 0) {
        float o0 = r0[0] + lin2b[0];
        float o1 = r1[0] + lin2b[1];
        float mx = fmaxf(o0, o1);
        float lse = mx + logf(expf(o0 - mx) + expf(o1 - mx));
        out[b * CCLS + 0] = o0 - lse;
        out[b * CCLS + 1] = o1 - lse;
    }
}

// ---------------- launcher ----------------
extern "C" void kernel_launch(void* const* d_in, const int* in_sizes, int n_in,
                              void* d_out, int out_size)
{
    const float* x     = (const float*)d_in[0];
    const int*   ei    = (const int*)d_in[2];   // int32 [2, E]
    const float* pe    = (const float*)d_in[3];
    const float* W1    = (const float*)d_in[4];
    const float* b1    = (const float*)d_in[5];
    const float* W2    = (const float*)d_in[6];
    const float* b2    = (const float*)d_in[7];
    const float* W3    = (const float*)d_in[8];
    const float* b3    = (const float*)d_in[9];
    const float* fcW   = (const float*)d_in[10];
    const float* fcb   = (const float*)d_in[11];
    const float* lin1W = (const float*)d_in[12];
    const float* lin1b = (const float*)d_in[13];
    const float* lin2W = (const float*)d_in[14];
    const float* lin2b = (const float*)d_in[15];
    float* out = (float*)d_out;

    __nv_bfloat16 *hwp, *h1p, *h2p, *ag1p, *wt1p, *wt2p, *wt3p;
    cudaGetSymbolAddress((void**)&hwp,  d_hw);
    cudaGetSymbolAddress((void**)&h1p,  d_h1);
    cudaGetSymbolAddress((void**)&h2p,  d_h2);
    cudaGetSymbolAddress((void**)&ag1p, d_ag1);
    cudaGetSymbolAddress((void**)&wt1p, d_wt1);
    cudaGetSymbolAddress((void**)&wt2p, d_wt2);
    cudaGetSymbolAddress((void**)&wt3p, d_wt3);
    int* degip; float* zaccp;
    cudaGetSymbolAddress((void**)&degip, d_degi);
    cudaGetSymbolAddress((void**)&zaccp, d_zacc);

    cudaFuncSetAttribute((void*)gemm_mma_kernel<K1PAD, true>,
                         cudaFuncAttributeMaxDynamicSharedMemorySize, GSM_BYTES);
    cudaFuncSetAttribute((void*)gemm_mma_kernel<HH, false>,
                         cudaFuncAttributeMaxDynamicSharedMemorySize, GSM_BYTES);

    // fused prep: degree count(+rank) + converts + transposes
    cudaMemsetAsync(degip, 0, NN * sizeof(int));
    prep_all_kernel<<<NB_PREP, 256>>>(ei, x, pe, W1, W2, W3);

    // CSR scan + atomic-free fill
    scan_part_kernel<<<SCANB, 1024>>>();
    scan_final_kernel<<<SCANB, 1024>>>();
    fill_csr_kernel<<<(EE + 255) / 256, 256>>>(ei);

    // layer 1: fused pre-aggregation (x + pe), then GEMM with bias+ELU -> h1
    gather_l1_kernel<<<GXB + NN, 128>>>();

    const dim3 ggrid((MM + 127) / 128, HH / 128);
    const uint4* hw4 = reinterpret_cast<const uint4*>(hwp);
    uint4* h24 = reinterpret_cast<uint4*>(h2p);

    gemm_mma_kernel<K1PAD, true><<<ggrid, 256, GSM_BYTES>>>(ag1p, wt1p, h1p, b1);

    // layer 2
    gemm_mma_kernel<HH, false><<<ggrid, 256, GSM_BYTES>>>(h1p, wt2p, hwp, nullptr);
    gather_kernel<false><<<NN, 128>>>(hw4, b2, h24, nullptr, nullptr);

    // layer 3 (+ fused fc head -> d_g)
    gemm_mma_kernel<HH, false><<<ggrid, 256, GSM_BYTES>>>(h2p, wt3p, hwp, nullptr);
    gather_kernel<true><<<NN, 128>>>(hw4, b3, nullptr, fcW, fcb);

    // heads
    cudaMemsetAsync(zaccp, 0, BSZ * HFCC * sizeof(float));
    lin1_kernel<<<dim3(HFCC / 128, (NN + NCH - 1) / NCH), 128>>>(lin1W);
    lin2_kernel<<<BSZ, 256>>>(lin1b, lin2W, lin2b, out);
}